// round 13
// baseline (speedup 1.0000x reference)
#include <cuda_runtime.h>
#include <cuda_fp16.h>
#include <math.h>

#define NB 256
#define NT 10
#define BT 2560
#define NP 49
#define VDIM 512
#define HDIM 256
#define ADIM 128
#define LDAH 528
#define LDQK2 260
#define LDATT 80

static __device__ __half g_wph[1409024];

#define OFF_QK   0
#define OFF_WV   131072
#define OFF_V31  393216
#define OFF_V2   786432
#define OFF_GA1  917504
#define OFF_GA2  983040
#define OFF_GAVE 1015808
#define OFF_GBN  1146880
#define OFF_GCA  1277952

__device__ __forceinline__ float wsum(float v){
#pragma unroll
    for (int s = 16; s > 0; s >>= 1) v += __shfl_xor_sync(0xffffffffu, v, s);
    return v;
}
__device__ __forceinline__ float wmax(float v){
#pragma unroll
    for (int s = 16; s > 0; s >>= 1) v = fmaxf(v, __shfl_xor_sync(0xffffffffu, v, s));
    return v;
}
__device__ __forceinline__ int posk(int k){
    int b = k & 15;
    return (k & ~15) + 4*((b & 7) >> 1) + 2*(b >> 3) + (b & 1);
}
__device__ __forceinline__ void mma16(float (&d)[4], unsigned a0, unsigned a1,
                                      unsigned a2, unsigned a3, unsigned b0, unsigned b1){
    asm volatile("mma.sync.aligned.m16n8k16.row.col.f32.f16.f16.f32 "
        "{%0,%1,%2,%3},{%4,%5,%6,%7},{%8,%9},{%0,%1,%2,%3};"
        : "+f"(d[0]), "+f"(d[1]), "+f"(d[2]), "+f"(d[3])
        : "r"(a0), "r"(a1), "r"(a2), "r"(a3), "r"(b0), "r"(b1));
}

// Quad-rowblock GEMM core: warp computes FOUR 16-row x 32-col tiles sharing one
// set of B fragments. Per k32: 4 B LDG.128 + 16 A LDS.64 for 32 HMMA
// (0.094 B/MAC vs 0.125 for the 32x32 dual tile).
template<int KH, class E>
__device__ __forceinline__ void gemm_quad(const __half* __restrict__ A0_,
                                          const __half* __restrict__ A1_,
                                          const __half* __restrict__ A2_,
                                          const __half* __restrict__ A3_,
                                          int ldah,
                                          const __half* __restrict__ B, int ntb, E epi)
{
    const int lane = threadIdx.x & 31;
    const int t = lane & 3;
    constexpr int nk32 = KH >> 5;
    float acc[4][4][4];
#pragma unroll
    for (int bl = 0; bl < 4; bl++)
#pragma unroll
    for (int nt = 0; nt < 4; nt++)
#pragma unroll
    for (int i = 0; i < 4; i++) acc[bl][nt][i] = 0.f;

    const __half* Ab[4] = {A0_, A1_, A2_, A3_};
    const __half* Bp = B + (size_t)ntb * nk32 * 256 + lane * 8;
#pragma unroll 2
    for (int k32 = 0; k32 < nk32; k32++){
        uint4 bv[4];
#pragma unroll
        for (int nt = 0; nt < 4; nt++)
            bv[nt] = *(const uint4*)(Bp + ((size_t)nt * nk32 + k32) * 256);
#pragma unroll
        for (int s = 0; s < 2; s++){
            const int k0 = k32*32 + s*16 + 4*t;
            uint2 lo[4], hi[4];
#pragma unroll
            for (int bl = 0; bl < 4; bl++){
                lo[bl] = *(const uint2*)(Ab[bl] + k0);
                hi[bl] = *(const uint2*)(Ab[bl] + 8*ldah + k0);
            }
#pragma unroll
            for (int nt = 0; nt < 4; nt++){
                unsigned b0 = s ? bv[nt].z : bv[nt].x;
                unsigned b1 = s ? bv[nt].w : bv[nt].y;
#pragma unroll
                for (int bl = 0; bl < 4; bl++)
                    mma16(acc[bl][nt], lo[bl].x, hi[bl].x, lo[bl].y, hi[bl].y, b0, b1);
            }
        }
    }
    epi(acc);
}

// 16-warp 2-item GEMV, fp16 weights, fp32 accumulate
template<int K, class F>
__device__ __forceinline__ void gemv16h(const __half* __restrict__ W,
                                        const float* __restrict__ x0,
                                        const float* __restrict__ x1, int N, F f){
    const int lane = threadIdx.x & 31, warp = threadIdx.x >> 5;
    for (int j = warp; j < N; j += 16){
        const __half* wr = W + (size_t)j * K;
        float s0 = 0.f, s1 = 0.f;
#pragma unroll
        for (int c = 0; c < K/128; c++){
            int idx = (lane + 32*c) * 4;
            uint2 w = *(const uint2*)(wr + idx);
            __half2 h01 = *(__half2*)&w.x, h23 = *(__half2*)&w.y;
            float2 a01 = __half22float2(h01), a23 = __half22float2(h23);
            float4 b0 = *(const float4*)(x0 + idx);
            float4 b1 = *(const float4*)(x1 + idx);
            s0 = fmaf(a01.x,b0.x, fmaf(a01.y,b0.y, fmaf(a23.x,b0.z, fmaf(a23.y,b0.w, s0))));
            s1 = fmaf(a01.x,b1.x, fmaf(a01.y,b1.y, fmaf(a23.x,b1.z, fmaf(a23.y,b1.w, s1))));
        }
        s0 = wsum(s0); s1 = wsum(s1);
        if (lane == 0) f(j, s0, s1);
    }
}

// ---- fused weight repack ----
__global__ void repack_all(const float* __restrict__ wq, const float* __restrict__ wk,
                           const float* __restrict__ wv, const float* __restrict__ w_v3,
                           const float* __restrict__ w_v1, const float* __restrict__ w_v2,
                           const float* __restrict__ w_a1, const float* __restrict__ w_a2,
                           const float* __restrict__ w_ave, const float* __restrict__ w_bn,
                           const float* __restrict__ w_ca)
{
    int i = blockIdx.x*blockDim.x + threadIdx.x;
    if (i >= 1409024) return;
    if (i >= 917504){
        const float* src; int base;
        if      (i < 983040)  { src = w_a1;  base = OFF_GA1; }
        else if (i < 1015808) { src = w_a2;  base = OFF_GA2; }
        else if (i < 1146880) { src = w_ave; base = OFF_GAVE; }
        else if (i < 1277952) { src = w_bn;  base = OFF_GBN; }
        else                  { src = w_ca;  base = OFF_GCA; }
        g_wph[i] = __float2half(src[i - base]);
        return;
    }
    const float* src; int base;
    if      (i < 65536)  { src = wq;   base = 0; }
    else if (i < 131072) { src = wk;   base = 65536; }
    else if (i < 393216) { src = wv;   base = 131072; }
    else if (i < 524288) { src = w_v3; base = 393216; }
    else if (i < 786432) { src = w_v1; base = 524288; }
    else                 { src = w_v2; base = 786432; }
    int li = i - base;
    int h = li & 7, r = li >> 3;
    int lane = r & 31; r >>= 5;
    int k32 = r & 15;  int nt = r >> 4;
    int g = lane >> 2, t = lane & 3;
    int s = h >> 2, hi = (h >> 1) & 1, lo = h & 1;
    int n = nt*8 + g;
    int k = k32*32 + 16*s + 8*hi + 2*t + lo;
    g_wph[i] = __float2half(src[(size_t)n*512 + k]);
}

// ---------------------------------------------------------------------------
// Fused kernel (2 items/CTA)
// ---------------------------------------------------------------------------
__global__ void __launch_bounds__(512, 1)
fused(const float* __restrict__ video, const float* __restrict__ audio,
      const float* __restrict__ bq, const float* __restrict__ bk,
      const float* __restrict__ bvb,
      const float* __restrict__ ln_g, const float* __restrict__ ln_b,
      const float* __restrict__ b_ave, const float* __restrict__ b_v3,
      const float* __restrict__ w_avatt, const float* __restrict__ b_avatt,
      const float* __restrict__ b_a1, const float* __restrict__ b_v1,
      const float* __restrict__ b_bn, const float* __restrict__ b_ca,
      const float* __restrict__ b_v2, const float* __restrict__ b_a2,
      const float* __restrict__ w_sa, const float* __restrict__ b_sa,
      float* __restrict__ out)
{
    extern __shared__ __align__(16) unsigned char smraw[];
    __half* sA0  = (__half*)smraw;                 // 64*528 h = 67584 B
    __half* sA1  = sA0 + 64*LDAH;                  // ends 135168
    __half* sQKb = (__half*)(smraw + 135168);      // qk phase: 66560 B
    __half* sZp  = (__half*)(smraw + 135168);      // Z phase: 65536 B (per item)
    float*  fbf  = (float*)(smraw + 135168);       // phase B: 2x3584 floats
    __half* sAtb = (__half*)(smraw + 201728);      // attn: 20480 B -> 222208
#define FB(it, off) (fbf + (it)*3584 + (off))

    const int tid = threadIdx.x, lane = tid & 31, warp = tid >> 5;
    const int g = lane >> 2, t = lane & 3;
    const int item0 = blockIdx.x * 2;
    const float* vf0 = video + (size_t)item0 * NP * VDIM;
    const float* vf1 = vf0 + NP * VDIM;

    // dual-item quad mapping for QK/V31/V2: mt2(2) x ng(8)
    const int mt2 = warp & 1, ng8 = warp >> 1;

    // ---- load vf -> sA fp16 permuted; zero pads + attn buffer ----
#pragma unroll
    for (int it = 0; it < 2; it++){
        __half* sA = it ? sA1 : sA0;
        const float* vf = it ? vf1 : vf0;
        for (int i = tid; i < NP*VDIM; i += 512)
            sA[(i >> 9)*LDAH + posk(i & 511)] = __float2half(vf[i]);
        for (int i = tid; i < 15*LDAH; i += 512)
            sA[49*LDAH + i] = __float2half(0.f);
    }
    for (int i = tid; i < 2*64*LDATT; i += 512) sAtb[i] = __float2half(0.f);
    __syncthreads();

    // ---- q|k GEMM (N=256): single pass, quad blocks = 2 rowhalves x 2 items ----
    {
        const int col0 = ng8*32;
        const __half* A0b = sA0 + (mt2*32 + g)*LDAH;
        const __half* A1b = A0b + 16*LDAH;
        const __half* A2b = sA1 + (mt2*32 + g)*LDAH;
        const __half* A3b = A2b + 16*LDAH;
        gemm_quad<512>(A0b, A1b, A2b, A3b, LDAH, g_wph + OFF_QK, col0 >> 3,
            [&](float (&a)[4][4][4]){
#pragma unroll
                for (int bl = 0; bl < 4; bl++){
                    int it = bl >> 1;
                    __half* dstb = sQKb + it*16640;
                    int rb = mt2*32 + (bl & 1)*16;
#pragma unroll
                    for (int h2 = 0; h2 < 2; h2++){
                        int r = rb + h2*8 + g;
#pragma unroll
                        for (int nt = 0; nt < 4; nt++)
#pragma unroll
                        for (int i = 0; i < 2; i++){
                            int c = col0 + nt*8 + 2*t + i;
                            float bb = (c < 128) ? bq[c] : bk[c-128];
                            dstb[r*LDQK2 + c] = __float2half(a[bl][nt][h2*2+i] + bb);
                        }
                    }
                }
            });
    }
    __syncthreads();

    // ---- softmax(q k^T): 98 rows over 16 warps ----
    for (int R = warp; R < 2*NP; R += 16){
        int it = (R >= NP) ? 1 : 0;
        int n = R - it*NP;
        const __half* q  = sQKb + it*16640 + n*LDQK2;
        const __half* kk = sQKb + it*16640 + 128;
        float a0 = 0.f, a1 = 0.f;
        const int m1 = lane + 32;
        const int m1c = (m1 < NP) ? m1 : 0;
        for (int j = 0; j < 128; j++){
            float qv = __half2float(q[j]);
            a0 = fmaf(qv, __half2float(kk[lane*LDQK2 + j]), a0);
            a1 = fmaf(qv, __half2float(kk[m1c *LDQK2 + j]), a1);
        }
        float v1 = (m1 < NP) ? a1 : -1e30f;
        float mx = wmax(fmaxf(a0, v1));
        float e0 = expf(a0 - mx);
        float e1 = (m1 < NP) ? expf(a1 - mx) : 0.f;
        float s = wsum(e0 + e1);
        float inv = 1.f / s;
        __half* att = sAtb + it*64*LDATT;
        att[n*LDATT + posk(lane)] = __float2half(e0 * inv);
        if (m1 < NP) att[n*LDATT + posk(m1)] = __float2half(e1 * inv);
    }
    __syncthreads();

    // ---- per item (sequential): Z = X @ Wv^T (1 pass, N=512); out = attn@Z ----
    for (int it = 0; it < 2; it++){
        const __half* sAi = it ? sA1 : sA0;
        __half* sAw = it ? sA1 : sA0;
        const float* vf = it ? vf1 : vf0;
        // Z GEMM: quad blocks = rows {0,16,32,48}, 16 warps = 16 col groups
        {
            const int col0 = warp*32;
            const __half* A0b = sAi + g*LDAH;
            gemm_quad<512>(A0b, A0b + 16*LDAH, A0b + 32*LDAH, A0b + 48*LDAH,
                           LDAH, g_wph + OFF_WV, col0 >> 3,
                [&](float (&a)[4][4][4]){
#pragma unroll
                    for (int bl = 0; bl < 4; bl++)
#pragma unroll
                    for (int h2 = 0; h2 < 2; h2++){
                        int m = bl*16 + h2*8 + g;
                        int k32 = m >> 5, b = m & 31;
                        int sb = b >> 4, rem = b & 15;
                        int hb = rem >> 3, tp = (rem >> 1) & 3, lo2 = rem & 1;
#pragma unroll
                        for (int nt = 0; nt < 4; nt++)
#pragma unroll
                        for (int i = 0; i < 2; i++){
                            int lc = col0 + nt*8 + 2*t + i;
                            int off = (((lc >> 3)*2 + k32)*32 + ((lc & 7)*4 + tp))*8
                                      + sb*4 + hb*2 + lo2;
                            sZp[off] = __float2half(a[bl][nt][h2*2+i]);
                        }
                    }
                });
        }
        __syncthreads();
        // attn@Z (1 pass, N=512): quad blocks = attn rows {0,16,32,48}
        {
            const int col0 = warp*32;
            const __half* A0b = sAtb + it*64*LDATT + g*LDATT;
            gemm_quad<64>(A0b, A0b + 16*LDATT, A0b + 32*LDATT, A0b + 48*LDATT,
                          LDATT, sZp, col0 >> 3,
                [&](float (&a)[4][4][4]){
#pragma unroll
                    for (int bl = 0; bl < 4; bl++)
#pragma unroll
                    for (int h2 = 0; h2 < 2; h2++){
                        int n = bl*16 + h2*8 + g;
                        if (n < NP){
#pragma unroll
                            for (int nt = 0; nt < 4; nt++)
#pragma unroll
                            for (int i = 0; i < 2; i++){
                                int c = col0 + nt*8 + 2*t + i;
                                float v = a[bl][nt][h2*2+i] + bvb[c] + vf[n*VDIM + c];
                                sAw[n*LDAH + posk(c)] = __float2half(v);
                            }
                        }
                    }
                });
        }
        __syncthreads();
    }

    // ---- LayerNorm in place on sA (rows < NP) ----
    for (int R = warp; R < 2*NP; R += 16){
        int it = (R >= NP) ? 1 : 0;
        int n = R - it*NP;
        __half* sA = it ? sA1 : sA0;
        float s = 0.f, s2 = 0.f;
        for (int j = lane; j < VDIM; j += 32){
            float v = __half2float(sA[n*LDAH + posk(j)]);
            s += v; s2 = fmaf(v, v, s2);
        }
        s = wsum(s); s2 = wsum(s2);
        float mu = s * (1.f/VDIM);
        float var = s2 * (1.f/VDIM) - mu*mu;
        float rs = rsqrtf(var + 1e-5f);
        for (int j = lane; j < VDIM; j += 32){
            float v = __half2float(sA[n*LDAH + posk(j)]);
            sA[n*LDAH + posk(j)] = __float2half((v - mu) * rs * ln_g[j] + ln_b[j]);
        }
    }
    __syncthreads();   // fbf region (was sZp) now safe to init
    {
        int b0 = item0 / NT, t0 = item0 % NT;
        int b1 = (item0+1) / NT, t1 = (item0+1) % NT;
        const float* ap0 = audio + ((size_t)t0 * NB + b0) * ADIM;
        const float* ap1 = audio + ((size_t)t1 * NB + b1) * ADIM;
        if (tid < ADIM){ FB(0,3328)[tid] = ap0[tid]; FB(1,3328)[tid] = ap1[tid]; }
        FB(0,1536)[tid] = 0.f;
        FB(1,1536)[tid] = 0.f;
        if (tid < 64){
#pragma unroll
            for (int it = 0; it < 2; it++){
                FB(it,3456)[tid] = (tid < NP) ? b_avatt[0] : 0.f;
                FB(it,3520)[tid] = (tid < NP) ? b_sa[0]   : 0.f;
            }
        }
    }
    __syncthreads();

    // ---- P1: colm, aq1, aq2 ----
    {
        int c = tid;
        int pc = posk(c);
        float s0 = 0.f, s1 = 0.f;
        for (int n = 0; n < NP; n++){
            s0 += __half2float(sA0[n*LDAH + pc]);
            s1 += __half2float(sA1[n*LDAH + pc]);
        }
        FB(0,0)[c] = s0 * (1.f/NP);
        FB(1,0)[c] = s1 * (1.f/NP);
    }
    gemv16h<ADIM>(g_wph + OFF_GA1, FB(0,3328), FB(1,3328), 512,
        [&](int j, float s0, float s1){
            FB(0,512)[j] = fmaxf(s0 + b_a1[j], 0.f);
            FB(1,512)[j] = fmaxf(s1 + b_a1[j], 0.f);
        });
    gemv16h<ADIM>(g_wph + OFF_GA2, FB(0,3328), FB(1,3328), 256,
        [&](int j, float s0, float s1){
            FB(0,2816)[j] = fmaxf(s0 + b_a2[j], 0.f);
            FB(1,2816)[j] = fmaxf(s1 + b_a2[j], 0.f);
        });
    __syncthreads();

    // ---- P2: havg ----
    gemv16h<VDIM>(g_wph + OFF_GAVE, FB(0,0), FB(1,0), 256,
        [&](int j, float s0, float s1){
            FB(0,2560)[j] = fmaxf(s0 + b_ave[j], 0.f);
            FB(1,2560)[j] = fmaxf(s1 + b_ave[j], 0.f);
        });
    __syncthreads();

    // ---- P3: combined [w_v3 | w_v1] GEMM (N=768): 3 passes of 256 ----
    {
        const __half* A0b = sA0 + (mt2*32 + g)*LDAH;
        const __half* A1b = A0b + 16*LDAH;
        const __half* A2b = sA1 + (mt2*32 + g)*LDAH;
        const __half* A3b = A2b + 16*LDAH;
        for (int p = 0; p < 3; p++){
            const int col0 = p*256 + ng8*32;
            gemm_quad<512>(A0b, A1b, A2b, A3b, LDAH, g_wph + OFF_V31, col0 >> 3,
                [&](float (&a)[4][4][4]){
                    if (col0 < 256){      // w_v3 -> self logits
#pragma unroll
                        for (int bl = 0; bl < 4; bl++){
                            int it = bl >> 1;
                            int rb = mt2*32 + (bl & 1)*16;
#pragma unroll
                            for (int h2 = 0; h2 < 2; h2++){
                                int r = rb + h2*8 + g;
                                float v = 0.f;
#pragma unroll
                                for (int nt = 0; nt < 4; nt++)
#pragma unroll
                                for (int i = 0; i < 2; i++){
                                    int c = col0 + nt*8 + 2*t + i;
                                    v += fmaxf(a[bl][nt][h2*2+i] + b_v3[c], 0.f)
                                         * FB(it,2560)[c] * w_avatt[c];
                                }
                                v += __shfl_xor_sync(0xffffffffu, v, 1);
                                v += __shfl_xor_sync(0xffffffffu, v, 2);
                                if (t == 0 && r < NP) atomicAdd(&FB(it,3456)[r], v);
                            }
                        }
                    } else {              // w_v1 -> colv partials
#pragma unroll
                        for (int it = 0; it < 2; it++){
                            int rb0 = mt2*32, rb1 = mt2*32 + 16;
#pragma unroll
                            for (int nt = 0; nt < 4; nt++)
#pragma unroll
                            for (int i = 0; i < 2; i++){
                                int c = col0 - 256 + nt*8 + 2*t + i;
                                float bb = b_v1[c];
                                float pv = 0.f;
#pragma unroll
                                for (int h2 = 0; h2 < 2; h2++){
                                    float m0 = (rb0 + h2*8 + g < NP) ? 1.f : 0.f;
                                    float m1 = (rb1 + h2*8 + g < NP) ? 1.f : 0.f;
                                    pv += m0*fmaxf(a[it*2][nt][h2*2+i]   + bb, 0.f)
                                        + m1*fmaxf(a[it*2+1][nt][h2*2+i] + bb, 0.f);
                                }
                                pv += __shfl_xor_sync(0xffffffffu, pv, 4);
                                pv += __shfl_xor_sync(0xffffffffu, pv, 8);
                                pv += __shfl_xor_sync(0xffffffffu, pv, 16);
                                if (g == 0) atomicAdd(&FB(it,1536)[c], pv);
                            }
                        }
                    }
                });
        }
    }
    __syncthreads();

    // ---- finalize colv; self softmax ----
    {
        int it = tid >> 8, c2 = (tid & 255)*2;
#pragma unroll
        for (int d = 0; d < 2; d++){
            int c = c2 + d;
            FB(it,1536)[c] = FB(it,1536)[c] * (1.f/NP) * FB(it,512)[c];
        }
    }
    if (warp < 2){
        int it = warp;
        float* sl = FB(it,3456);
        float v0 = tanhf(sl[lane]);
        float v1 = (lane + 32 < NP) ? tanhf(sl[lane+32]) : -1e30f;
        float mx = wmax(fmaxf(v0, v1));
        float e0 = expf(v0 - mx);
        float e1 = (lane + 32 < NP) ? expf(v1 - mx) : 0.f;
        float s = wsum(e0 + e1);
        sl[lane] = e0 / s;
        if (lane + 32 < NP) sl[lane+32] = e1 / s;
    }
    __syncthreads();

    // ---- P4: avq = relu(W_bn colv) ----
    gemv16h<VDIM>(g_wph + OFF_GBN, FB(0,1536), FB(1,1536), 256,
        [&](int j, float s0, float s1){
            FB(0,3072)[j] = fmaxf(s0 + b_bn[j], 0.f);
            FB(1,3072)[j] = fmaxf(s1 + b_bn[j], 0.f);
        });
    __syncthreads();

    // ---- P5: sav = self_maps @ vf2 ; ch = 1 + sigmoid(W_ca avq) ----
    {
        int c = tid; int pc = posk(c);
        float s0 = 0.f, s1 = 0.f;
        for (int n = 0; n < NP; n++){
            s0 = fmaf(FB(0,3456)[n], __half2float(sA0[n*LDAH + pc]), s0);
            s1 = fmaf(FB(1,3456)[n], __half2float(sA1[n*LDAH + pc]), s1);
        }
        FB(0,2048)[c] = s0; FB(1,2048)[c] = s1;
    }
    gemv16h<HDIM>(g_wph + OFF_GCA, FB(0,3072), FB(1,3072), 512,
        [&](int j, float s0, float s1){
            FB(0,1024)[j] = 1.f + 1.f/(1.f + expf(-(s0 + b_ca[j])));
            FB(1,1024)[j] = 1.f + 1.f/(1.f + expf(-(s1 + b_ca[j])));
        });
    __syncthreads();

    // ---- P6: overwrite sA with c_att = video * ch ----
#pragma unroll
    for (int it = 0; it < 2; it++){
        __half* sA = it ? sA1 : sA0;
        const float* vf = it ? vf1 : vf0;
        const float* ch = FB(it,1024);
        for (int i = tid; i < NP*VDIM; i += 512){
            int c = i & 511;
            sA[(i >> 9)*LDAH + posk(c)] = __float2half(vf[i] * ch[c]);
        }
    }
    __syncthreads();

    // ---- P7: w_v2 GEMM -> spatial logits (N=256): single pass ----
    {
        const int col0 = ng8*32;
        const __half* A0b = sA0 + (mt2*32 + g)*LDAH;
        const __half* A1b = A0b + 16*LDAH;
        const __half* A2b = sA1 + (mt2*32 + g)*LDAH;
        const __half* A3b = A2b + 16*LDAH;
        gemm_quad<512>(A0b, A1b, A2b, A3b, LDAH, g_wph + OFF_V2, col0 >> 3,
            [&](float (&a)[4][4][4]){
#pragma unroll
                for (int bl = 0; bl < 4; bl++){
                    int it = bl >> 1;
                    int rb = mt2*32 + (bl & 1)*16;
#pragma unroll
                    for (int h2 = 0; h2 < 2; h2++){
                        int r = rb + h2*8 + g;
                        float v = 0.f;
#pragma unroll
                        for (int nt = 0; nt < 4; nt++)
#pragma unroll
                        for (int i = 0; i < 2; i++){
                            int c = col0 + nt*8 + 2*t + i;
                            v += fmaxf(a[bl][nt][h2*2+i] + b_v2[c], 0.f)
                                 * FB(it,2816)[c] * w_sa[c];
                        }
                        v += __shfl_xor_sync(0xffffffffu, v, 1);
                        v += __shfl_xor_sync(0xffffffffu, v, 2);
                        if (t == 0 && r < NP) atomicAdd(&FB(it,3520)[r], v);
                    }
                }
            });
    }
    __syncthreads();

    // ---- P8: spatial softmax ----
    if (warp < 2){
        int it = warp;
        float* sp = FB(it,3520);
        float v0 = tanhf(sp[lane]);
        float v1 = (lane + 32 < NP) ? tanhf(sp[lane+32]) : -1e30f;
        float mx = wmax(fmaxf(v0, v1));
        float e0 = expf(v0 - mx);
        float e1 = (lane + 32 < NP) ? expf(v1 - mx) : 0.f;
        float s = wsum(e0 + e1);
        sp[lane] = e0 / s;
        if (lane + 32 < NP) sp[lane+32] = e1 / s;
    }
    __syncthreads();

    // ---- P9: outputs ----
    {
        int c = tid; int pc = posk(c);
        float cs0 = 0.f, cs1 = 0.f;
        for (int n = 0; n < NP; n++){
            cs0 = fmaf(FB(0,3520)[n], __half2float(sA0[n*LDAH + pc]), cs0);
            cs1 = fmaf(FB(1,3520)[n], __half2float(sA1[n*LDAH + pc]), cs1);
        }
        float g0 = 1.f + 0.5f/(1.f + expf(-FB(0,2048)[c]));
        float g1 = 1.f + 0.5f/(1.f + expf(-FB(1,2048)[c]));
        out[(size_t)item0*VDIM + c]     = cs0 * g0;
        out[(size_t)(item0+1)*VDIM + c] = cs1 * g1;
    }
    if (tid < ADIM){
        out[(size_t)BT*VDIM + (size_t)item0*ADIM + tid]     = FB(0,3328)[tid];
        out[(size_t)BT*VDIM + (size_t)(item0+1)*ADIM + tid] = FB(1,3328)[tid];
    }
#undef FB
}

// ---------------------------------------------------------------------------
extern "C" void kernel_launch(void* const* d_in, const int* in_sizes, int n_in,
                              void* d_out, int out_size)
{
    const float* video = (const float*)d_in[0];
    const float* audio = (const float*)d_in[1];
    const float* wq    = (const float*)d_in[2];  const float* bq    = (const float*)d_in[3];
    const float* wk    = (const float*)d_in[4];  const float* bk    = (const float*)d_in[5];
    const float* wv    = (const float*)d_in[6];  const float* bv    = (const float*)d_in[7];
    const float* ln_g  = (const float*)d_in[8];  const float* ln_b  = (const float*)d_in[9];
    const float* w_ave = (const float*)d_in[10]; const float* b_ave = (const float*)d_in[11];
    const float* w_v3  = (const float*)d_in[12]; const float* b_v3  = (const float*)d_in[13];
    const float* w_avt = (const float*)d_in[14]; const float* b_avt = (const float*)d_in[15];
    const float* w_a1  = (const float*)d_in[16]; const float* b_a1  = (const float*)d_in[17];
    const float* w_v1  = (const float*)d_in[18]; const float* b_v1  = (const float*)d_in[19];
    const float* w_bn  = (const float*)d_in[20]; const float* b_bn  = (const float*)d_in[21];
    const float* w_ca  = (const float*)d_in[22]; const float* b_ca  = (const float*)d_in[23];
    const float* w_v2  = (const float*)d_in[24]; const float* b_v2  = (const float*)d_in[25];
    const float* w_a2  = (const float*)d_in[26]; const float* b_a2  = (const float*)d_in[27];
    const float* w_sa  = (const float*)d_in[28]; const float* b_sa  = (const float*)d_in[29];
    float* out = (float*)d_out;

    repack_all<<<5504, 256>>>(wq, wk, wv, w_v3, w_v1, w_v2,
                              w_a1, w_a2, w_ave, w_bn, w_ca);

    const int smem = 222208;
    cudaFuncSetAttribute(fused, cudaFuncAttributeMaxDynamicSharedMemorySize, smem);
    fused<<<BT/2, 512, smem>>>(video, audio, bq, bk, bv, ln_g, ln_b,
                               b_ave, b_v3, w_avt, b_avt, b_a1, b_v1,
                               b_bn, b_ca, b_v2, b_a2, w_sa, b_sa, out);
}

// round 15
// speedup vs baseline: 1.1932x; 1.1932x over previous
#include <cuda_runtime.h>
#include <cuda_fp16.h>
#include <math.h>

#define NB 256
#define NT 10
#define BT 2560
#define NP 49
#define VDIM 512
#define HDIM 256
#define ADIM 128
#define LDAH 520
#define LDAHB 1040
#define LDQK2 260
#define LDATT 72
#define LDATTB 144

static __device__ __half g_wph[1409024];

#define OFF_QK   0
#define OFF_WV   131072
#define OFF_V31  393216
#define OFF_V2   786432
#define OFF_GA1  917504
#define OFF_GA2  983040
#define OFF_GAVE 1015808
#define OFF_GBN  1146880
#define OFF_GCA  1277952

// smem map (bytes): sA [0,133120) = 2 items x 64 x LDAH halves
// SM_R1 [133120,199680): qk buf (66560) | sZp (65536) | fbf (28672)
// SM_R2 [199680,218112): attn 2 x 64 x LDATT halves (18432)
#define SM_R1 133120
#define SM_R2 199680
#define SMEM_TOTAL 218112

__device__ __forceinline__ unsigned smem_u32(const void* p){
    unsigned a;
    asm("{ .reg .u64 t; cvta.to.shared.u64 t, %1; cvt.u32.u64 %0, t; }" : "=r"(a) : "l"(p));
    return a;
}
__device__ __forceinline__ float wsum(float v){
#pragma unroll
    for (int s = 16; s > 0; s >>= 1) v += __shfl_xor_sync(0xffffffffu, v, s);
    return v;
}
__device__ __forceinline__ float wmax(float v){
#pragma unroll
    for (int s = 16; s > 0; s >>= 1) v = fmaxf(v, __shfl_xor_sync(0xffffffffu, v, s));
    return v;
}
__device__ __forceinline__ void mma16(float (&d)[4], unsigned a0, unsigned a1,
                                      unsigned a2, unsigned a3, unsigned b0, unsigned b1){
    asm volatile("mma.sync.aligned.m16n8k16.row.col.f32.f16.f16.f32 "
        "{%0,%1,%2,%3},{%4,%5,%6,%7},{%8,%9},{%0,%1,%2,%3};"
        : "+f"(d[0]), "+f"(d[1]), "+f"(d[2]), "+f"(d[3])
        : "r"(a0), "r"(a1), "r"(a2), "r"(a3), "r"(b0), "r"(b1));
}
__device__ __forceinline__ void ldsm4(unsigned (&r)[4], unsigned a){
    asm volatile("ldmatrix.sync.aligned.m8n8.x4.shared.b16 {%0,%1,%2,%3}, [%4];"
        : "=r"(r[0]), "=r"(r[1]), "=r"(r[2]), "=r"(r[3]) : "r"(a));
}

// Quad-rowblock GEMM core, ldmatrix A path. ab[bl] = shared addr of block bl's
// lane-resolved base: blockRow0 + (lane&15)*ldahB + (lane>>4)*16, k=0.
// B: packed fragment layout in global (L1-shared across warps).
template<int KH, class E>
__device__ __forceinline__ void gemm_quad(unsigned ab0, unsigned ab1,
                                          unsigned ab2, unsigned ab3,
                                          const __half* __restrict__ B, int ntb, E epi)
{
    const int lane = threadIdx.x & 31;
    constexpr int nk32 = KH >> 5;
    float acc[4][4][4];
#pragma unroll
    for (int bl = 0; bl < 4; bl++)
#pragma unroll
    for (int nt = 0; nt < 4; nt++)
#pragma unroll
    for (int i = 0; i < 4; i++) acc[bl][nt][i] = 0.f;

    const unsigned ab[4] = {ab0, ab1, ab2, ab3};
    const __half* Bp = B + (size_t)ntb * nk32 * 256 + lane * 8;
#pragma unroll 2
    for (int k32 = 0; k32 < nk32; k32++){
        uint4 bv[4];
#pragma unroll
        for (int nt = 0; nt < 4; nt++)
            bv[nt] = *(const uint4*)(Bp + ((size_t)nt * nk32 + k32) * 256);
#pragma unroll
        for (int s = 0; s < 2; s++){
            const unsigned ko = (unsigned)(k32*64 + s*32);
            unsigned R[4][4];
#pragma unroll
            for (int bl = 0; bl < 4; bl++) ldsm4(R[bl], ab[bl] + ko);
#pragma unroll
            for (int nt = 0; nt < 4; nt++){
                unsigned b0 = s ? bv[nt].z : bv[nt].x;
                unsigned b1 = s ? bv[nt].w : bv[nt].y;
#pragma unroll
                for (int bl = 0; bl < 4; bl++)
                    mma16(acc[bl][nt], R[bl][0], R[bl][1], R[bl][2], R[bl][3], b0, b1);
            }
        }
    }
    epi(acc);
}

template<int K, class F>
__device__ __forceinline__ void gemv16h(const __half* __restrict__ W,
                                        const float* __restrict__ x0,
                                        const float* __restrict__ x1, int N, F f){
    const int lane = threadIdx.x & 31, warp = threadIdx.x >> 5;
    for (int j = warp; j < N; j += 16){
        const __half* wr = W + (size_t)j * K;
        float s0 = 0.f, s1 = 0.f;
#pragma unroll
        for (int c = 0; c < K/128; c++){
            int idx = (lane + 32*c) * 4;
            uint2 w = *(const uint2*)(wr + idx);
            __half2 h01 = *(__half2*)&w.x, h23 = *(__half2*)&w.y;
            float2 a01 = __half22float2(h01), a23 = __half22float2(h23);
            float4 b0 = *(const float4*)(x0 + idx);
            float4 b1 = *(const float4*)(x1 + idx);
            s0 = fmaf(a01.x,b0.x, fmaf(a01.y,b0.y, fmaf(a23.x,b0.z, fmaf(a23.y,b0.w, s0))));
            s1 = fmaf(a01.x,b1.x, fmaf(a01.y,b1.y, fmaf(a23.x,b1.z, fmaf(a23.y,b1.w, s1))));
        }
        s0 = wsum(s0); s1 = wsum(s1);
        if (lane == 0) f(j, s0, s1);
    }
}

__global__ void repack_all(const float* __restrict__ wq, const float* __restrict__ wk,
                           const float* __restrict__ wv, const float* __restrict__ w_v3,
                           const float* __restrict__ w_v1, const float* __restrict__ w_v2,
                           const float* __restrict__ w_a1, const float* __restrict__ w_a2,
                           const float* __restrict__ w_ave, const float* __restrict__ w_bn,
                           const float* __restrict__ w_ca)
{
    int i = blockIdx.x*blockDim.x + threadIdx.x;
    if (i >= 1409024) return;
    if (i >= 917504){
        const float* src; int base;
        if      (i < 983040)  { src = w_a1;  base = OFF_GA1; }
        else if (i < 1015808) { src = w_a2;  base = OFF_GA2; }
        else if (i < 1146880) { src = w_ave; base = OFF_GAVE; }
        else if (i < 1277952) { src = w_bn;  base = OFF_GBN; }
        else                  { src = w_ca;  base = OFF_GCA; }
        g_wph[i] = __float2half(src[i - base]);
        return;
    }
    const float* src; int base;
    if      (i < 65536)  { src = wq;   base = 0; }
    else if (i < 131072) { src = wk;   base = 65536; }
    else if (i < 393216) { src = wv;   base = 131072; }
    else if (i < 524288) { src = w_v3; base = 393216; }
    else if (i < 786432) { src = w_v1; base = 524288; }
    else                 { src = w_v2; base = 786432; }
    int li = i - base;
    int h = li & 7, r = li >> 3;
    int lane = r & 31; r >>= 5;
    int k32 = r & 15;  int nt = r >> 4;
    int g = lane >> 2, t = lane & 3;
    int s = h >> 2, hi = (h >> 1) & 1, lo = h & 1;
    g_wph[i] = __float2half(src[(size_t)(nt*8 + g)*512 + k32*32 + 16*s + 8*hi + 2*t + lo]);
}

__global__ void __launch_bounds__(512, 1)
fused(const float* __restrict__ video, const float* __restrict__ audio,
      const float* __restrict__ bq, const float* __restrict__ bk,
      const float* __restrict__ bvb,
      const float* __restrict__ ln_g, const float* __restrict__ ln_b,
      const float* __restrict__ b_ave, const float* __restrict__ b_v3,
      const float* __restrict__ w_avatt, const float* __restrict__ b_avatt,
      const float* __restrict__ b_a1, const float* __restrict__ b_v1,
      const float* __restrict__ b_bn, const float* __restrict__ b_ca,
      const float* __restrict__ b_v2, const float* __restrict__ b_a2,
      const float* __restrict__ w_sa, const float* __restrict__ b_sa,
      float* __restrict__ out)
{
    extern __shared__ __align__(16) unsigned char smraw[];
    __half* sA   = (__half*)smraw;                 // 2 x 64 x LDAH, row-major
    __half* sQKb = (__half*)(smraw + SM_R1);
    __half* sZp  = (__half*)(smraw + SM_R1);
    float*  fbf  = (float*)(smraw + SM_R1);
    __half* sAtb = (__half*)(smraw + SM_R2);
#define FB(it, off) (fbf + (it)*3584 + (off))
    // colm 0, aq1 512, ch 1024, colv 1536, sav 2048, havg 2560,
    // aq2 2816, avqv 3072, aud 3328, sSelf 3456, sSp 3520

    const int tid = threadIdx.x, lane = tid & 31, warp = tid >> 5;
    const int g = lane >> 2, t = lane & 3;
    const int item0 = blockIdx.x * 2;
    const float* vf0 = video + (size_t)item0 * NP * VDIM;
    const float* vf1 = vf0 + NP * VDIM;
    const unsigned smb = smem_u32(smraw);
    const unsigned laneOff  = (unsigned)((lane & 15) * LDAHB  + ((lane >> 4) << 4));
    const unsigned laneOffA = (unsigned)((lane & 15) * LDATTB + ((lane >> 4) << 4));
    const int mt2 = warp & 1, ng8 = warp >> 1;

    // ---- load vf -> sA (plain rows, vectorized); zero pads + attn ----
#pragma unroll
    for (int it = 0; it < 2; it++){
        __half* sAi = sA + it*64*LDAH;
        const float* vf = it ? vf1 : vf0;
        for (int i = tid; i < NP*VDIM/4; i += 512){
            int row = i >> 7, c4 = (i & 127) << 2;
            float4 v = ((const float4*)vf)[i];
            __half2 h01 = __floats2half2_rn(v.x, v.y);
            __half2 h23 = __floats2half2_rn(v.z, v.w);
            *(uint2*)(sAi + row*LDAH + c4) = make_uint2(*(unsigned*)&h01, *(unsigned*)&h23);
        }
        for (int i = tid; i < 15*LDAH; i += 512) sAi[49*LDAH + i] = __float2half(0.f);
    }
    for (int i = tid; i < 2*64*LDATT; i += 512) sAtb[i] = __float2half(0.f);
    __syncthreads();

    // ---- q|k GEMM (N=256): quad = 2 rowhalves x 2 items ----
    {
        const int col0 = ng8*32;
        unsigned a0 = smb + (unsigned)(mt2*32)*LDAHB + laneOff;
        unsigned a1 = a0 + 16*LDAHB;
        unsigned a2 = a0 + 64*LDAHB;
        unsigned a3 = a2 + 16*LDAHB;
        gemm_quad<512>(a0, a1, a2, a3, g_wph + OFF_QK, col0 >> 3,
            [&](float (&a)[4][4][4]){
#pragma unroll
                for (int bl = 0; bl < 4; bl++){
                    int it = bl >> 1;
                    __half* dstb = sQKb + it*16640;
                    int rb = mt2*32 + (bl & 1)*16;
#pragma unroll
                    for (int h2 = 0; h2 < 2; h2++){
                        int r = rb + h2*8 + g;
#pragma unroll
                        for (int nt = 0; nt < 4; nt++)
#pragma unroll
                        for (int i = 0; i < 2; i++){
                            int c = col0 + nt*8 + 2*t + i;
                            float bb = (c < 128) ? bq[c] : bk[c-128];
                            dstb[r*LDQK2 + c] = __float2half(a[bl][nt][h2*2+i] + bb);
                        }
                    }
                }
            });
    }
    __syncthreads();

    // ---- softmax(q k^T): 98 rows / 16 warps ----
    for (int R = warp; R < 2*NP; R += 16){
        int it = (R >= NP) ? 1 : 0;
        int n = R - it*NP;
        const __half* q  = sQKb + it*16640 + n*LDQK2;
        const __half* kk = sQKb + it*16640 + 128;
        float a0 = 0.f, a1 = 0.f;
        const int m1 = lane + 32, m1c = (m1 < NP) ? m1 : 0;
        for (int j = 0; j < 128; j++){
            float qv = __half2float(q[j]);
            a0 = fmaf(qv, __half2float(kk[lane*LDQK2 + j]), a0);
            a1 = fmaf(qv, __half2float(kk[m1c *LDQK2 + j]), a1);
        }
        float v1 = (m1 < NP) ? a1 : -1e30f;
        float mx = wmax(fmaxf(a0, v1));
        float e0 = expf(a0 - mx);
        float e1 = (m1 < NP) ? expf(a1 - mx) : 0.f;
        float s = wsum(e0 + e1);
        float inv = 1.f / s;
        __half* att = sAtb + it*64*LDATT;
        att[n*LDATT + lane] = __float2half(e0 * inv);
        if (m1 < NP) att[n*LDATT + m1] = __float2half(e1 * inv);
    }
    __syncthreads();

    // ---- per item: Z = X@Wv^T -> packed sZp; attn@Z -> sA (pre-LN) ----
    for (int it = 0; it < 2; it++){
        const float* vf = it ? vf1 : vf0;
        __half* sAw = sA + (size_t)it*64*LDAH;
        {   // Z: quad rows {0,16,32,48} of item it; 16 warps x 32 cols
            const int col0 = warp*32;
            unsigned a0 = smb + (unsigned)(it*64)*LDAHB + laneOff;
            gemm_quad<512>(a0, a0+16*LDAHB, a0+32*LDAHB, a0+48*LDAHB,
                           g_wph + OFF_WV, col0 >> 3,
                [&](float (&a)[4][4][4]){
#pragma unroll
                    for (int bl = 0; bl < 4; bl++)
#pragma unroll
                    for (int h2 = 0; h2 < 2; h2++){
                        int m = bl*16 + h2*8 + g;
                        int k32 = m >> 5, b = m & 31;
                        int sb = b >> 4, rem = b & 15;
                        int hb = rem >> 3, tp = (rem >> 1) & 3, lo2 = rem & 1;
#pragma unroll
                        for (int nt = 0; nt < 4; nt++)
#pragma unroll
                        for (int i = 0; i < 2; i++){
                            int lc = col0 + nt*8 + 2*t + i;
                            int off = (((lc >> 3)*2 + k32)*32 + ((lc & 7)*4 + tp))*8
                                      + sb*4 + hb*2 + lo2;
                            sZp[off] = __float2half(a[bl][nt][h2*2+i]);
                        }
                    }
                });
        }
        __syncthreads();
        {   // attn@Z: A = attn rows (K=64)
            const int col0 = warp*32;
            unsigned a0 = smb + SM_R2 + (unsigned)(it*64)*LDATTB + laneOffA;
            gemm_quad<64>(a0, a0+16*LDATTB, a0+32*LDATTB, a0+48*LDATTB,
                          sZp, col0 >> 3,
                [&](float (&a)[4][4][4]){
#pragma unroll
                    for (int bl = 0; bl < 4; bl++)
#pragma unroll
                    for (int h2 = 0; h2 < 2; h2++){
                        int n = bl*16 + h2*8 + g;
                        if (n < NP){
#pragma unroll
                            for (int nt = 0; nt < 4; nt++)
#pragma unroll
                            for (int i = 0; i < 2; i++){
                                int c = col0 + nt*8 + 2*t + i;
                                float v = a[bl][nt][h2*2+i] + bvb[c] + vf[n*VDIM + c];
                                sAw[n*LDAH + c] = __float2half(v);
                            }
                        }
                    }
                });
        }
        __syncthreads();
    }

    // ---- LayerNorm in place on sA ----
    for (int R = warp; R < 2*NP; R += 16){
        int it = (R >= NP) ? 1 : 0;
        int n = R - it*NP;
        __half* row = sA + (size_t)it*64*LDAH + n*LDAH;
        float s = 0.f, s2 = 0.f;
        for (int j = lane; j < VDIM; j += 32){
            float v = __half2float(row[j]);
            s += v; s2 = fmaf(v, v, s2);
        }
        s = wsum(s); s2 = wsum(s2);
        float mu = s * (1.f/VDIM);
        float var = s2 * (1.f/VDIM) - mu*mu;
        float rs = rsqrtf(var + 1e-5f);
        for (int j = lane; j < VDIM; j += 32){
            float v = __half2float(row[j]);
            row[j] = __float2half((v - mu) * rs * ln_g[j] + ln_b[j]);
        }
    }
    __syncthreads();
    {
        int b0 = item0 / NT, t0 = item0 % NT;
        int b1 = (item0+1) / NT, t1 = (item0+1) % NT;
        const float* ap0 = audio + ((size_t)t0 * NB + b0) * ADIM;
        const float* ap1 = audio + ((size_t)t1 * NB + b1) * ADIM;
        if (tid < ADIM){ FB(0,3328)[tid] = ap0[tid]; FB(1,3328)[tid] = ap1[tid]; }
        FB(0,1536)[tid] = 0.f;
        FB(1,1536)[tid] = 0.f;
        if (tid < 64){
#pragma unroll
            for (int it = 0; it < 2; it++){
                FB(it,3456)[tid] = (tid < NP) ? b_avatt[0] : 0.f;
                FB(it,3520)[tid] = (tid < NP) ? b_sa[0]   : 0.f;
            }
        }
    }
    __syncthreads();

    // ---- P1: colm, aq1, aq2 ----
    {
        int c = tid;
        float s0 = 0.f, s1 = 0.f;
        for (int n = 0; n < NP; n++){
            s0 += __half2float(sA[n*LDAH + c]);
            s1 += __half2float(sA[(64+n)*LDAH + c]);
        }
        FB(0,0)[c] = s0 * (1.f/NP);
        FB(1,0)[c] = s1 * (1.f/NP);
    }
    gemv16h<ADIM>(g_wph + OFF_GA1, FB(0,3328), FB(1,3328), 512,
        [&](int j, float s0, float s1){
            FB(0,512)[j] = fmaxf(s0 + b_a1[j], 0.f);
            FB(1,512)[j] = fmaxf(s1 + b_a1[j], 0.f);
        });
    gemv16h<ADIM>(g_wph + OFF_GA2, FB(0,3328), FB(1,3328), 256,
        [&](int j, float s0, float s1){
            FB(0,2816)[j] = fmaxf(s0 + b_a2[j], 0.f);
            FB(1,2816)[j] = fmaxf(s1 + b_a2[j], 0.f);
        });
    __syncthreads();
    gemv16h<VDIM>(g_wph + OFF_GAVE, FB(0,0), FB(1,0), 256,
        [&](int j, float s0, float s1){
            FB(0,2560)[j] = fmaxf(s0 + b_ave[j], 0.f);
            FB(1,2560)[j] = fmaxf(s1 + b_ave[j], 0.f);
        });
    __syncthreads();

    // ---- P3: [w_v3 | w_v1] GEMM (N=768): 3 passes of 256 ----
    {
        unsigned a0 = smb + (unsigned)(mt2*32)*LDAHB + laneOff;
        unsigned a1 = a0 + 16*LDAHB;
        unsigned a2 = a0 + 64*LDAHB;
        unsigned a3 = a2 + 16*LDAHB;
        for (int p = 0; p < 3; p++){
            const int col0 = p*256 + ng8*32;
            gemm_quad<512>(a0, a1, a2, a3, g_wph + OFF_V31, col0 >> 3,
                [&](float (&a)[4][4][4]){
                    if (col0 < 256){
#pragma unroll
                        for (int bl = 0; bl < 4; bl++){
                            int it = bl >> 1;
                            int rb = mt2*32 + (bl & 1)*16;
#pragma unroll
                            for (int h2 = 0; h2 < 2; h2++){
                                int r = rb + h2*8 + g;
                                float v = 0.f;
#pragma unroll
                                for (int nt = 0; nt < 4; nt++)
#pragma unroll
                                for (int i = 0; i < 2; i++){
                                    int c = col0 + nt*8 + 2*t + i;
                                    v += fmaxf(a[bl][nt][h2*2+i] + b_v3[c], 0.f)
                                         * FB(it,2560)[c] * w_avatt[c];
                                }
                                v += __shfl_xor_sync(0xffffffffu, v, 1);
                                v += __shfl_xor_sync(0xffffffffu, v, 2);
                                if (t == 0 && r < NP) atomicAdd(&FB(it,3456)[r], v);
                            }
                        }
                    } else {
#pragma unroll
                        for (int it = 0; it < 2; it++){
                            int rb0 = mt2*32, rb1 = mt2*32 + 16;
#pragma unroll
                            for (int nt = 0; nt < 4; nt++)
#pragma unroll
                            for (int i = 0; i < 2; i++){
                                int c = col0 - 256 + nt*8 + 2*t + i;
                                float bb = b_v1[c];
                                float pv = 0.f;
#pragma unroll
                                for (int h2 = 0; h2 < 2; h2++){
                                    float m0 = (rb0 + h2*8 + g < NP) ? 1.f : 0.f;
                                    float m1 = (rb1 + h2*8 + g < NP) ? 1.f : 0.f;
                                    pv += m0*fmaxf(a[it*2][nt][h2*2+i]   + bb, 0.f)
                                        + m1*fmaxf(a[it*2+1][nt][h2*2+i] + bb, 0.f);
                                }
                                pv += __shfl_xor_sync(0xffffffffu, pv, 4);
                                pv += __shfl_xor_sync(0xffffffffu, pv, 8);
                                pv += __shfl_xor_sync(0xffffffffu, pv, 16);
                                if (g == 0) atomicAdd(&FB(it,1536)[c], pv);
                            }
                        }
                    }
                });
        }
    }
    __syncthreads();

    // ---- finalize colv; self softmax ----
    {
        int it = tid >> 8, c2 = (tid & 255)*2;
#pragma unroll
        for (int d = 0; d < 2; d++){
            int c = c2 + d;
            FB(it,1536)[c] = FB(it,1536)[c] * (1.f/NP) * FB(it,512)[c];
        }
    }
    if (warp < 2){
        float* sl = FB(warp,3456);
        float v0 = tanhf(sl[lane]);
        float v1 = (lane + 32 < NP) ? tanhf(sl[lane+32]) : -1e30f;
        float mx = wmax(fmaxf(v0, v1));
        float e0 = expf(v0 - mx);
        float e1 = (lane + 32 < NP) ? expf(v1 - mx) : 0.f;
        float s = wsum(e0 + e1);
        sl[lane] = e0 / s;
        if (lane + 32 < NP) sl[lane+32] = e1 / s;
    }
    __syncthreads();
    gemv16h<VDIM>(g_wph + OFF_GBN, FB(0,1536), FB(1,1536), 256,
        [&](int j, float s0, float s1){
            FB(0,3072)[j] = fmaxf(s0 + b_bn[j], 0.f);
            FB(1,3072)[j] = fmaxf(s1 + b_bn[j], 0.f);
        });
    __syncthreads();

    // ---- P5: sav ; ch ----
    {
        int c = tid;
        float s0 = 0.f, s1 = 0.f;
        for (int n = 0; n < NP; n++){
            s0 = fmaf(FB(0,3456)[n], __half2float(sA[n*LDAH + c]), s0);
            s1 = fmaf(FB(1,3456)[n], __half2float(sA[(64+n)*LDAH + c]), s1);
        }
        FB(0,2048)[c] = s0; FB(1,2048)[c] = s1;
    }
    gemv16h<HDIM>(g_wph + OFF_GCA, FB(0,3072), FB(1,3072), 512,
        [&](int j, float s0, float s1){
            FB(0,1024)[j] = 1.f + 1.f/(1.f + expf(-(s0 + b_ca[j])));
            FB(1,1024)[j] = 1.f + 1.f/(1.f + expf(-(s1 + b_ca[j])));
        });
    __syncthreads();

    // ---- P6: c_att = video * ch -> sA ----
#pragma unroll
    for (int it = 0; it < 2; it++){
        __half* sAi = sA + (size_t)it*64*LDAH;
        const float* vf = it ? vf1 : vf0;
        const float* ch = FB(it,1024);
        for (int i = tid; i < NP*VDIM/4; i += 512){
            int row = i >> 7, c4 = (i & 127) << 2;
            float4 v = ((const float4*)vf)[i];
            __half2 h01 = __floats2half2_rn(v.x*ch[c4],   v.y*ch[c4+1]);
            __half2 h23 = __floats2half2_rn(v.z*ch[c4+2], v.w*ch[c4+3]);
            *(uint2*)(sAi + row*LDAH + c4) = make_uint2(*(unsigned*)&h01, *(unsigned*)&h23);
        }
    }
    __syncthreads();

    // ---- P7: w_v2 GEMM -> spatial logits ----
    {
        const int col0 = ng8*32;
        unsigned a0 = smb + (unsigned)(mt2*32)*LDAHB + laneOff;
        unsigned a1 = a0 + 16*LDAHB;
        unsigned a2 = a0 + 64*LDAHB;
        unsigned a3 = a2 + 16*LDAHB;
        gemm_quad<512>(a0, a1, a2, a3, g_wph + OFF_V2, col0 >> 3,
            [&](float (&a)[4][4][4]){
#pragma unroll
                for (int bl = 0; bl < 4; bl++){
                    int it = bl >> 1;
                    int rb = mt2*32 + (bl & 1)*16;
#pragma unroll
                    for (int h2 = 0; h2 < 2; h2++){
                        int r = rb + h2*8 + g;
                        float v = 0.f;
#pragma unroll
                        for (int nt = 0; nt < 4; nt++)
#pragma unroll
                        for (int i = 0; i < 2; i++){
                            int c = col0 + nt*8 + 2*t + i;
                            v += fmaxf(a[bl][nt][h2*2+i] + b_v2[c], 0.f)
                                 * FB(it,2816)[c] * w_sa[c];
                        }
                        v += __shfl_xor_sync(0xffffffffu, v, 1);
                        v += __shfl_xor_sync(0xffffffffu, v, 2);
                        if (t == 0 && r < NP) atomicAdd(&FB(it,3520)[r], v);
                    }
                }
            });
    }
    __syncthreads();

    // ---- spatial softmax ----
    if (warp < 2){
        float* sp = FB(warp,3520);
        float v0 = tanhf(sp[lane]);
        float v1 = (lane + 32 < NP) ? tanhf(sp[lane+32]) : -1e30f;
        float mx = wmax(fmaxf(v0, v1));
        float e0 = expf(v0 - mx);
        float e1 = (lane + 32 < NP) ? expf(v1 - mx) : 0.f;
        float s = wsum(e0 + e1);
        sp[lane] = e0 / s;
        if (lane + 32 < NP) sp[lane+32] = e1 / s;
    }
    __syncthreads();

    // ---- outputs ----
    {
        int c = tid;
        float cs0 = 0.f, cs1 = 0.f;
        for (int n = 0; n < NP; n++){
            cs0 = fmaf(FB(0,3520)[n], __half2float(sA[n*LDAH + c]), cs0);
            cs1 = fmaf(FB(1,3520)[n], __half2float(sA[(64+n)*LDAH + c]), cs1);
        }
        float g0 = 1.f + 0.5f/(1.f + expf(-FB(0,2048)[c]));
        float g1 = 1.f + 0.5f/(1.f + expf(-FB(1,2048)[c]));
        out[(size_t)item0*VDIM + c]     = cs0 * g0;
        out[(size_t)(item0+1)*VDIM + c] = cs1 * g1;
    }
    if (tid < ADIM){
        out[(size_t)BT*VDIM + (size_t)item0*ADIM + tid]     = FB(0,3328)[tid];
        out[(size_t)BT*VDIM + (size_t)(item0+1)*ADIM + tid] = FB(1,3328)[tid];
    }
#undef FB
}

extern "C" void kernel_launch(void* const* d_in, const int* in_sizes, int n_in,
                              void* d_out, int out_size)
{
    const float* video = (const float*)d_in[0];
    const float* audio = (const float*)d_in[1];
    const float* wq    = (const float*)d_in[2];  const float* bq    = (const float*)d_in[3];
    const float* wk    = (const float*)d_in[4];  const float* bk    = (const float*)d_in[5];
    const float* wv    = (const float*)d_in[6];  const float* bv    = (const float*)d_in[7];
    const float* ln_g  = (const float*)d_in[8];  const float* ln_b  = (const float*)d_in[9];
    const float* w_ave = (const float*)d_in[10]; const float* b_ave = (const float*)d_in[11];
    const float* w_v3  = (const float*)d_in[12]; const float* b_v3  = (const float*)d_in[13];
    const float* w_avt = (const float*)d_in[14]; const float* b_avt = (const float*)d_in[15];
    const float* w_a1  = (const float*)d_in[16]; const float* b_a1  = (const float*)d_in[17];
    const float* w_v1  = (const float*)d_in[18]; const float* b_v1  = (const float*)d_in[19];
    const float* w_bn  = (const float*)d_in[20]; const float* b_bn  = (const float*)d_in[21];
    const float* w_ca  = (const float*)d_in[22]; const float* b_ca  = (const float*)d_in[23];
    const float* w_v2  = (const float*)d_in[24]; const float* b_v2  = (const float*)d_in[25];
    const float* w_a2  = (const float*)d_in[26]; const float* b_a2  = (const float*)d_in[27];
    const float* w_sa  = (const float*)d_in[28]; const float* b_sa  = (const float*)d_in[29];
    float* out = (float*)d_out;

    repack_all<<<5504, 256>>>(wq, wk, wv, w_v3, w_v1, w_v2,
                              w_a1, w_a2, w_ave, w_bn, w_ca);

    cudaFuncSetAttribute(fused, cudaFuncAttributeMaxDynamicSharedMemorySize, SMEM_TOTAL);
    fused<<<BT/2, 512, SMEM_TOTAL>>>(video, audio, bq, bk, bv, ln_g, ln_b,
                                     b_ave, b_v3, w_avt, b_avt, b_a1, b_v1,
                                     b_bn, b_ca, b_v2, b_a2, w_sa, b_sa, out);
}

// round 16
// speedup vs baseline: 1.2287x; 1.0298x over previous
#include <cuda_runtime.h>
#include <cuda_fp16.h>
#include <math.h>

#define NB 256
#define NT 10
#define BT 2560
#define NP 49
#define VDIM 512
#define HDIM 256
#define ADIM 128
#define LDAH 520
#define LDAHB 1040
#define LDQK2 260
#define LDATT 72
#define LDATTB 144

static __device__ __half g_wph[1409024];

#define OFF_QK   0
#define OFF_WV   131072
#define OFF_V31  393216
#define OFF_V2   786432
#define OFF_GA1  917504
#define OFF_GA2  983040
#define OFF_GAVE 1015808
#define OFF_GBN  1146880
#define OFF_GCA  1277952

#define SM_R1 133120
#define SM_R2 199680
#define SMEM_TOTAL 218112

__device__ __forceinline__ unsigned smem_u32(const void* p){
    unsigned a;
    asm("{ .reg .u64 t; cvta.to.shared.u64 t, %1; cvt.u32.u64 %0, t; }" : "=r"(a) : "l"(p));
    return a;
}
__device__ __forceinline__ float wsum(float v){
#pragma unroll
    for (int s = 16; s > 0; s >>= 1) v += __shfl_xor_sync(0xffffffffu, v, s);
    return v;
}
__device__ __forceinline__ float wmax(float v){
#pragma unroll
    for (int s = 16; s > 0; s >>= 1) v = fmaxf(v, __shfl_xor_sync(0xffffffffu, v, s));
    return v;
}
__device__ __forceinline__ void mma16(float (&d)[4], unsigned a0, unsigned a1,
                                      unsigned a2, unsigned a3, unsigned b0, unsigned b1){
    asm volatile("mma.sync.aligned.m16n8k16.row.col.f32.f16.f16.f32 "
        "{%0,%1,%2,%3},{%4,%5,%6,%7},{%8,%9},{%0,%1,%2,%3};"
        : "+f"(d[0]), "+f"(d[1]), "+f"(d[2]), "+f"(d[3])
        : "r"(a0), "r"(a1), "r"(a2), "r"(a3), "r"(b0), "r"(b1));
}
__device__ __forceinline__ void ldsm4(unsigned (&r)[4], unsigned a){
    asm volatile("ldmatrix.sync.aligned.m8n8.x4.shared.b16 {%0,%1,%2,%3}, [%4];"
        : "=r"(r[0]), "=r"(r[1]), "=r"(r[2]), "=r"(r[3]) : "r"(a));
}

// Quad-rowblock GEMM, ldmatrix A, register double-buffered B prefetch.
template<int KH, class E>
__device__ __forceinline__ void gemm_quad(unsigned ab0, unsigned ab1,
                                          unsigned ab2, unsigned ab3,
                                          const __half* __restrict__ B, int ntb, E epi)
{
    const int lane = threadIdx.x & 31;
    constexpr int nk32 = KH >> 5;
    float acc[4][4][4];
#pragma unroll
    for (int bl = 0; bl < 4; bl++)
#pragma unroll
    for (int nt = 0; nt < 4; nt++)
#pragma unroll
    for (int i = 0; i < 4; i++) acc[bl][nt][i] = 0.f;

    const unsigned ab[4] = {ab0, ab1, ab2, ab3};
    const __half* Bp = B + (size_t)ntb * nk32 * 256 + lane * 8;
    uint4 bv[4];
#pragma unroll
    for (int nt = 0; nt < 4; nt++)
        bv[nt] = *(const uint4*)(Bp + (size_t)nt * nk32 * 256);
#pragma unroll
    for (int k32 = 0; k32 < nk32; k32++){
        uint4 bn[4];
        if (k32 + 1 < nk32){
#pragma unroll
            for (int nt = 0; nt < 4; nt++)
                bn[nt] = *(const uint4*)(Bp + ((size_t)nt * nk32 + k32 + 1) * 256);
        }
#pragma unroll
        for (int s = 0; s < 2; s++){
            const unsigned ko = (unsigned)(k32*64 + s*32);
            unsigned R[4][4];
#pragma unroll
            for (int bl = 0; bl < 4; bl++) ldsm4(R[bl], ab[bl] + ko);
#pragma unroll
            for (int nt = 0; nt < 4; nt++){
                unsigned b0 = s ? bv[nt].z : bv[nt].x;
                unsigned b1 = s ? bv[nt].w : bv[nt].y;
#pragma unroll
                for (int bl = 0; bl < 4; bl++)
                    mma16(acc[bl][nt], R[bl][0], R[bl][1], R[bl][2], R[bl][3], b0, b1);
            }
        }
#pragma unroll
        for (int nt = 0; nt < 4; nt++) bv[nt] = bn[nt];
    }
    epi(acc);
}

template<int K, class F>
__device__ __forceinline__ void gemv16h(const __half* __restrict__ W,
                                        const float* __restrict__ x0,
                                        const float* __restrict__ x1, int N, F f){
    const int lane = threadIdx.x & 31, warp = threadIdx.x >> 5;
    for (int j = warp; j < N; j += 16){
        const __half* wr = W + (size_t)j * K;
        float s0 = 0.f, s1 = 0.f;
#pragma unroll
        for (int c = 0; c < K/128; c++){
            int idx = (lane + 32*c) * 4;
            uint2 w = *(const uint2*)(wr + idx);
            __half2 h01 = *(__half2*)&w.x, h23 = *(__half2*)&w.y;
            float2 a01 = __half22float2(h01), a23 = __half22float2(h23);
            float4 b0 = *(const float4*)(x0 + idx);
            float4 b1 = *(const float4*)(x1 + idx);
            s0 = fmaf(a01.x,b0.x, fmaf(a01.y,b0.y, fmaf(a23.x,b0.z, fmaf(a23.y,b0.w, s0))));
            s1 = fmaf(a01.x,b1.x, fmaf(a01.y,b1.y, fmaf(a23.x,b1.z, fmaf(a23.y,b1.w, s1))));
        }
        s0 = wsum(s0); s1 = wsum(s1);
        if (lane == 0) f(j, s0, s1);
    }
}

__global__ void repack_all(const float* __restrict__ wq, const float* __restrict__ wk,
                           const float* __restrict__ wv, const float* __restrict__ w_v3,
                           const float* __restrict__ w_v1, const float* __restrict__ w_v2,
                           const float* __restrict__ w_a1, const float* __restrict__ w_a2,
                           const float* __restrict__ w_ave, const float* __restrict__ w_bn,
                           const float* __restrict__ w_ca)
{
    int i = blockIdx.x*blockDim.x + threadIdx.x;
    if (i >= 1409024) return;
    if (i >= 917504){
        const float* src; int base;
        if      (i < 983040)  { src = w_a1;  base = OFF_GA1; }
        else if (i < 1015808) { src = w_a2;  base = OFF_GA2; }
        else if (i < 1146880) { src = w_ave; base = OFF_GAVE; }
        else if (i < 1277952) { src = w_bn;  base = OFF_GBN; }
        else                  { src = w_ca;  base = OFF_GCA; }
        g_wph[i] = __float2half(src[i - base]);
        return;
    }
    const float* src; int base;
    if      (i < 65536)  { src = wq;   base = 0; }
    else if (i < 131072) { src = wk;   base = 65536; }
    else if (i < 393216) { src = wv;   base = 131072; }
    else if (i < 524288) { src = w_v3; base = 393216; }
    else if (i < 786432) { src = w_v1; base = 524288; }
    else                 { src = w_v2; base = 786432; }
    int li = i - base;
    int h = li & 7, r = li >> 3;
    int lane = r & 31; r >>= 5;
    int k32 = r & 15;  int nt = r >> 4;
    int g = lane >> 2, t = lane & 3;
    int s = h >> 2, hi = (h >> 1) & 1, lo = h & 1;
    g_wph[i] = __float2half(src[(size_t)(nt*8 + g)*512 + k32*32 + 16*s + 8*hi + 2*t + lo]);
}

__global__ void __launch_bounds__(512, 1)
fused(const float* __restrict__ video, const float* __restrict__ audio,
      const float* __restrict__ bq, const float* __restrict__ bk,
      const float* __restrict__ bvb,
      const float* __restrict__ ln_g, const float* __restrict__ ln_b,
      const float* __restrict__ b_ave, const float* __restrict__ b_v3,
      const float* __restrict__ w_avatt, const float* __restrict__ b_avatt,
      const float* __restrict__ b_a1, const float* __restrict__ b_v1,
      const float* __restrict__ b_bn, const float* __restrict__ b_ca,
      const float* __restrict__ b_v2, const float* __restrict__ b_a2,
      const float* __restrict__ w_sa, const float* __restrict__ b_sa,
      float* __restrict__ out)
{
    extern __shared__ __align__(16) unsigned char smraw[];
    __half* sA   = (__half*)smraw;
    __half* sQKb = (__half*)(smraw + SM_R1);
    __half* sZp  = (__half*)(smraw + SM_R1);
    float*  fbf  = (float*)(smraw + SM_R1);
    __half* sAtb = (__half*)(smraw + SM_R2);
#define FB(it, off) (fbf + (it)*3584 + (off))

    const int tid = threadIdx.x, lane = tid & 31, warp = tid >> 5;
    const int g = lane >> 2, t = lane & 3;
    const int item0 = blockIdx.x * 2;
    const float* vf0 = video + (size_t)item0 * NP * VDIM;
    const float* vf1 = vf0 + NP * VDIM;
    const unsigned smb = smem_u32(smraw);
    const unsigned laneOff  = (unsigned)((lane & 15) * LDAHB  + ((lane >> 4) << 4));
    const unsigned laneOffA = (unsigned)((lane & 15) * LDATTB + ((lane >> 4) << 4));
    const int mt2 = warp & 1, ng8 = warp >> 1;

#pragma unroll
    for (int it = 0; it < 2; it++){
        __half* sAi = sA + it*64*LDAH;
        const float* vf = it ? vf1 : vf0;
        for (int i = tid; i < NP*VDIM/4; i += 512){
            int row = i >> 7, c4 = (i & 127) << 2;
            float4 v = ((const float4*)vf)[i];
            __half2 h01 = __floats2half2_rn(v.x, v.y);
            __half2 h23 = __floats2half2_rn(v.z, v.w);
            *(uint2*)(sAi + row*LDAH + c4) = make_uint2(*(unsigned*)&h01, *(unsigned*)&h23);
        }
        for (int i = tid; i < 15*LDAH; i += 512) sAi[49*LDAH + i] = __float2half(0.f);
    }
    for (int i = tid; i < 2*64*LDATT; i += 512) sAtb[i] = __float2half(0.f);
    __syncthreads();

    // ---- q|k GEMM ----
    {
        const int col0 = ng8*32;
        unsigned a0 = smb + (unsigned)(mt2*32)*LDAHB + laneOff;
        unsigned a1 = a0 + 16*LDAHB;
        unsigned a2 = a0 + 64*LDAHB;
        unsigned a3 = a2 + 16*LDAHB;
        gemm_quad<512>(a0, a1, a2, a3, g_wph + OFF_QK, col0 >> 3,
            [&](float (&a)[4][4][4]){
#pragma unroll
                for (int bl = 0; bl < 4; bl++){
                    int it = bl >> 1;
                    __half* dstb = sQKb + it*16640;
                    int rb = mt2*32 + (bl & 1)*16;
#pragma unroll
                    for (int h2 = 0; h2 < 2; h2++){
                        int r = rb + h2*8 + g;
#pragma unroll
                        for (int nt = 0; nt < 4; nt++)
#pragma unroll
                        for (int i = 0; i < 2; i++){
                            int c = col0 + nt*8 + 2*t + i;
                            float bb = (c < 128) ? bq[c] : bk[c-128];
                            dstb[r*LDQK2 + c] = __float2half(a[bl][nt][h2*2+i] + bb);
                        }
                    }
                }
            });
    }
    __syncthreads();

    // ---- softmax(q k^T): vectorized dot (4 halves per load) ----
    for (int R = warp; R < 2*NP; R += 16){
        int it = (R >= NP) ? 1 : 0;
        int n = R - it*NP;
        const __half* q  = sQKb + it*16640 + n*LDQK2;
        const __half* kk = sQKb + it*16640 + 128;
        float a0 = 0.f, a1 = 0.f;
        const int m1 = lane + 32, m1c = (m1 < NP) ? m1 : 0;
        const __half* k0p = kk + lane*LDQK2;
        const __half* k1p = kk + m1c*LDQK2;
#pragma unroll 8
        for (int j = 0; j < 128; j += 4){
            uint2 qw = *(const uint2*)(q + j);
            uint2 k0w = *(const uint2*)(k0p + j);
            uint2 k1w = *(const uint2*)(k1p + j);
            float2 qa = __half22float2(*(__half2*)&qw.x);
            float2 qb = __half22float2(*(__half2*)&qw.y);
            float2 xa = __half22float2(*(__half2*)&k0w.x);
            float2 xb = __half22float2(*(__half2*)&k0w.y);
            float2 ya = __half22float2(*(__half2*)&k1w.x);
            float2 yb = __half22float2(*(__half2*)&k1w.y);
            a0 = fmaf(qa.x,xa.x, fmaf(qa.y,xa.y, fmaf(qb.x,xb.x, fmaf(qb.y,xb.y, a0))));
            a1 = fmaf(qa.x,ya.x, fmaf(qa.y,ya.y, fmaf(qb.x,yb.x, fmaf(qb.y,yb.y, a1))));
        }
        float v1 = (m1 < NP) ? a1 : -1e30f;
        float mx = wmax(fmaxf(a0, v1));
        float e0 = expf(a0 - mx);
        float e1 = (m1 < NP) ? expf(a1 - mx) : 0.f;
        float s = wsum(e0 + e1);
        float inv = 1.f / s;
        __half* att = sAtb + it*64*LDATT;
        att[n*LDATT + lane] = __float2half(e0 * inv);
        if (m1 < NP) att[n*LDATT + m1] = __float2half(e1 * inv);
    }
    __syncthreads();

    // ---- per item: Z -> sZp; attn@Z -> sA (pre-LN) ----
    for (int it = 0; it < 2; it++){
        const float* vf = it ? vf1 : vf0;
        __half* sAw = sA + (size_t)it*64*LDAH;
        {
            const int col0 = warp*32;
            unsigned a0 = smb + (unsigned)(it*64)*LDAHB + laneOff;
            gemm_quad<512>(a0, a0+16*LDAHB, a0+32*LDAHB, a0+48*LDAHB,
                           g_wph + OFF_WV, col0 >> 3,
                [&](float (&a)[4][4][4]){
#pragma unroll
                    for (int bl = 0; bl < 4; bl++)
#pragma unroll
                    for (int h2 = 0; h2 < 2; h2++){
                        int m = bl*16 + h2*8 + g;
                        int k32 = m >> 5, b = m & 31;
                        int sb = b >> 4, rem = b & 15;
                        int hb = rem >> 3, tp = (rem >> 1) & 3, lo2 = rem & 1;
#pragma unroll
                        for (int nt = 0; nt < 4; nt++)
#pragma unroll
                        for (int i = 0; i < 2; i++){
                            int lc = col0 + nt*8 + 2*t + i;
                            int off = (((lc >> 3)*2 + k32)*32 + ((lc & 7)*4 + tp))*8
                                      + sb*4 + hb*2 + lo2;
                            sZp[off] = __float2half(a[bl][nt][h2*2+i]);
                        }
                    }
                });
        }
        __syncthreads();
        {
            const int col0 = warp*32;
            unsigned a0 = smb + SM_R2 + (unsigned)(it*64)*LDATTB + laneOffA;
            gemm_quad<64>(a0, a0+16*LDATTB, a0+32*LDATTB, a0+48*LDATTB,
                          sZp, col0 >> 3,
                [&](float (&a)[4][4][4]){
#pragma unroll
                    for (int bl = 0; bl < 4; bl++)
#pragma unroll
                    for (int h2 = 0; h2 < 2; h2++){
                        int n = bl*16 + h2*8 + g;
                        if (n < NP){
#pragma unroll
                            for (int nt = 0; nt < 4; nt++)
#pragma unroll
                            for (int i = 0; i < 2; i++){
                                int c = col0 + nt*8 + 2*t + i;
                                float v = a[bl][nt][h2*2+i] + bvb[c] + vf[n*VDIM + c];
                                sAw[n*LDAH + c] = __float2half(v);
                            }
                        }
                    }
                });
        }
        __syncthreads();
    }

    // ---- LayerNorm in place ----
    for (int R = warp; R < 2*NP; R += 16){
        int it = (R >= NP) ? 1 : 0;
        int n = R - it*NP;
        __half* row = sA + (size_t)it*64*LDAH + n*LDAH;
        float s = 0.f, s2 = 0.f;
        for (int j = lane; j < VDIM; j += 32){
            float v = __half2float(row[j]);
            s += v; s2 = fmaf(v, v, s2);
        }
        s = wsum(s); s2 = wsum(s2);
        float mu = s * (1.f/VDIM);
        float var = s2 * (1.f/VDIM) - mu*mu;
        float rs = rsqrtf(var + 1e-5f);
        for (int j = lane; j < VDIM; j += 32){
            float v = __half2float(row[j]);
            row[j] = __float2half((v - mu) * rs * ln_g[j] + ln_b[j]);
        }
    }
    __syncthreads();
    {
        int b0 = item0 / NT, t0 = item0 % NT;
        int b1 = (item0+1) / NT, t1 = (item0+1) % NT;
        const float* ap0 = audio + ((size_t)t0 * NB + b0) * ADIM;
        const float* ap1 = audio + ((size_t)t1 * NB + b1) * ADIM;
        if (tid < ADIM){ FB(0,3328)[tid] = ap0[tid]; FB(1,3328)[tid] = ap1[tid]; }
        FB(0,1536)[tid] = 0.f;
        FB(1,1536)[tid] = 0.f;
        if (tid < 64){
#pragma unroll
            for (int it = 0; it < 2; it++){
                FB(it,3456)[tid] = (tid < NP) ? b_avatt[0] : 0.f;
                FB(it,3520)[tid] = (tid < NP) ? b_sa[0]   : 0.f;
            }
        }
    }
    __syncthreads();

    // ---- P1: colm, aq1, aq2 ----
    {
        int c = tid;
        float s0 = 0.f, s1 = 0.f;
        for (int n = 0; n < NP; n++){
            s0 += __half2float(sA[n*LDAH + c]);
            s1 += __half2float(sA[(64+n)*LDAH + c]);
        }
        FB(0,0)[c] = s0 * (1.f/NP);
        FB(1,0)[c] = s1 * (1.f/NP);
    }
    gemv16h<ADIM>(g_wph + OFF_GA1, FB(0,3328), FB(1,3328), 512,
        [&](int j, float s0, float s1){
            FB(0,512)[j] = fmaxf(s0 + b_a1[j], 0.f);
            FB(1,512)[j] = fmaxf(s1 + b_a1[j], 0.f);
        });
    gemv16h<ADIM>(g_wph + OFF_GA2, FB(0,3328), FB(1,3328), 256,
        [&](int j, float s0, float s1){
            FB(0,2816)[j] = fmaxf(s0 + b_a2[j], 0.f);
            FB(1,2816)[j] = fmaxf(s1 + b_a2[j], 0.f);
        });
    __syncthreads();
    gemv16h<VDIM>(g_wph + OFF_GAVE, FB(0,0), FB(1,0), 256,
        [&](int j, float s0, float s1){
            FB(0,2560)[j] = fmaxf(s0 + b_ave[j], 0.f);
            FB(1,2560)[j] = fmaxf(s1 + b_ave[j], 0.f);
        });
    __syncthreads();

    // ---- P3: [w_v3 | w_v1] GEMM, 3 passes of 256 ----
    {
        unsigned a0 = smb + (unsigned)(mt2*32)*LDAHB + laneOff;
        unsigned a1 = a0 + 16*LDAHB;
        unsigned a2 = a0 + 64*LDAHB;
        unsigned a3 = a2 + 16*LDAHB;
        for (int p = 0; p < 3; p++){
            const int col0 = p*256 + ng8*32;
            gemm_quad<512>(a0, a1, a2, a3, g_wph + OFF_V31, col0 >> 3,
                [&](float (&a)[4][4][4]){
                    if (col0 < 256){
#pragma unroll
                        for (int bl = 0; bl < 4; bl++){
                            int it = bl >> 1;
                            int rb = mt2*32 + (bl & 1)*16;
#pragma unroll
                            for (int h2 = 0; h2 < 2; h2++){
                                int r = rb + h2*8 + g;
                                float v = 0.f;
#pragma unroll
                                for (int nt = 0; nt < 4; nt++)
#pragma unroll
                                for (int i = 0; i < 2; i++){
                                    int c = col0 + nt*8 + 2*t + i;
                                    v += fmaxf(a[bl][nt][h2*2+i] + b_v3[c], 0.f)
                                         * FB(it,2560)[c] * w_avatt[c];
                                }
                                v += __shfl_xor_sync(0xffffffffu, v, 1);
                                v += __shfl_xor_sync(0xffffffffu, v, 2);
                                if (t == 0 && r < NP) atomicAdd(&FB(it,3456)[r], v);
                            }
                        }
                    } else {
#pragma unroll
                        for (int it = 0; it < 2; it++){
                            int rb0 = mt2*32, rb1 = mt2*32 + 16;
#pragma unroll
                            for (int nt = 0; nt < 4; nt++)
#pragma unroll
                            for (int i = 0; i < 2; i++){
                                int c = col0 - 256 + nt*8 + 2*t + i;
                                float bb = b_v1[c];
                                float pv = 0.f;
#pragma unroll
                                for (int h2 = 0; h2 < 2; h2++){
                                    float m0 = (rb0 + h2*8 + g < NP) ? 1.f : 0.f;
                                    float m1 = (rb1 + h2*8 + g < NP) ? 1.f : 0.f;
                                    pv += m0*fmaxf(a[it*2][nt][h2*2+i]   + bb, 0.f)
                                        + m1*fmaxf(a[it*2+1][nt][h2*2+i] + bb, 0.f);
                                }
                                pv += __shfl_xor_sync(0xffffffffu, pv, 4);
                                pv += __shfl_xor_sync(0xffffffffu, pv, 8);
                                pv += __shfl_xor_sync(0xffffffffu, pv, 16);
                                if (g == 0) atomicAdd(&FB(it,1536)[c], pv);
                            }
                        }
                    }
                });
        }
    }
    __syncthreads();

    // ---- finalize colv; self softmax ----
    {
        int it = tid >> 8, c2 = (tid & 255)*2;
#pragma unroll
        for (int d = 0; d < 2; d++){
            int c = c2 + d;
            FB(it,1536)[c] = FB(it,1536)[c] * (1.f/NP) * FB(it,512)[c];
        }
    }
    if (warp < 2){
        float* sl = FB(warp,3456);
        float v0 = tanhf(sl[lane]);
        float v1 = (lane + 32 < NP) ? tanhf(sl[lane+32]) : -1e30f;
        float mx = wmax(fmaxf(v0, v1));
        float e0 = expf(v0 - mx);
        float e1 = (lane + 32 < NP) ? expf(v1 - mx) : 0.f;
        float s = wsum(e0 + e1);
        sl[lane] = e0 / s;
        if (lane + 32 < NP) sl[lane+32] = e1 / s;
    }
    __syncthreads();
    gemv16h<VDIM>(g_wph + OFF_GBN, FB(0,1536), FB(1,1536), 256,
        [&](int j, float s0, float s1){
            FB(0,3072)[j] = fmaxf(s0 + b_bn[j], 0.f);
            FB(1,3072)[j] = fmaxf(s1 + b_bn[j], 0.f);
        });
    __syncthreads();

    // ---- P5: sav ; ch ----
    {
        int c = tid;
        float s0 = 0.f, s1 = 0.f;
        for (int n = 0; n < NP; n++){
            s0 = fmaf(FB(0,3456)[n], __half2float(sA[n*LDAH + c]), s0);
            s1 = fmaf(FB(1,3456)[n], __half2float(sA[(64+n)*LDAH + c]), s1);
        }
        FB(0,2048)[c] = s0; FB(1,2048)[c] = s1;
    }
    gemv16h<HDIM>(g_wph + OFF_GCA, FB(0,3072), FB(1,3072), 512,
        [&](int j, float s0, float s1){
            FB(0,1024)[j] = 1.f + 1.f/(1.f + expf(-(s0 + b_ca[j])));
            FB(1,1024)[j] = 1.f + 1.f/(1.f + expf(-(s1 + b_ca[j])));
        });
    __syncthreads();

    // ---- P6: c_att -> sA ----
#pragma unroll
    for (int it = 0; it < 2; it++){
        __half* sAi = sA + (size_t)it*64*LDAH;
        const float* vf = it ? vf1 : vf0;
        const float* ch = FB(it,1024);
        for (int i = tid; i < NP*VDIM/4; i += 512){
            int row = i >> 7, c4 = (i & 127) << 2;
            float4 v = ((const float4*)vf)[i];
            __half2 h01 = __floats2half2_rn(v.x*ch[c4],   v.y*ch[c4+1]);
            __half2 h23 = __floats2half2_rn(v.z*ch[c4+2], v.w*ch[c4+3]);
            *(uint2*)(sAi + row*LDAH + c4) = make_uint2(*(unsigned*)&h01, *(unsigned*)&h23);
        }
    }
    __syncthreads();

    // ---- P7: w_v2 GEMM -> spatial logits ----
    {
        const int col0 = ng8*32;
        unsigned a0 = smb + (unsigned)(mt2*32)*LDAHB + laneOff;
        unsigned a1 = a0 + 16*LDAHB;
        unsigned a2 = a0 + 64*LDAHB;
        unsigned a3 = a2 + 16*LDAHB;
        gemm_quad<512>(a0, a1, a2, a3, g_wph + OFF_V2, col0 >> 3,
            [&](float (&a)[4][4][4]){
#pragma unroll
                for (int bl = 0; bl < 4; bl++){
                    int it = bl >> 1;
                    int rb = mt2*32 + (bl & 1)*16;
#pragma unroll
                    for (int h2 = 0; h2 < 2; h2++){
                        int r = rb + h2*8 + g;
                        float v = 0.f;
#pragma unroll
                        for (int nt = 0; nt < 4; nt++)
#pragma unroll
                        for (int i = 0; i < 2; i++){
                            int c = col0 + nt*8 + 2*t + i;
                            v += fmaxf(a[bl][nt][h2*2+i] + b_v2[c], 0.f)
                                 * FB(it,2816)[c] * w_sa[c];
                        }
                        v += __shfl_xor_sync(0xffffffffu, v, 1);
                        v += __shfl_xor_sync(0xffffffffu, v, 2);
                        if (t == 0 && r < NP) atomicAdd(&FB(it,3520)[r], v);
                    }
                }
            });
    }
    __syncthreads();

    // ---- spatial softmax ----
    if (warp < 2){
        float* sp = FB(warp,3520);
        float v0 = tanhf(sp[lane]);
        float v1 = (lane + 32 < NP) ? tanhf(sp[lane+32]) : -1e30f;
        float mx = wmax(fmaxf(v0, v1));
        float e0 = expf(v0 - mx);
        float e1 = (lane + 32 < NP) ? expf(v1 - mx) : 0.f;
        float s = wsum(e0 + e1);
        sp[lane] = e0 / s;
        if (lane + 32 < NP) sp[lane+32] = e1 / s;
    }
    __syncthreads();

    // ---- outputs ----
    {
        int c = tid;
        float cs0 = 0.f, cs1 = 0.f;
        for (int n = 0; n < NP; n++){
            cs0 = fmaf(FB(0,3520)[n], __half2float(sA[n*LDAH + c]), cs0);
            cs1 = fmaf(FB(1,3520)[n], __half2float(sA[(64+n)*LDAH + c]), cs1);
        }
        float g0 = 1.f + 0.5f/(1.f + expf(-FB(0,2048)[c]));
        float g1 = 1.f + 0.5f/(1.f + expf(-FB(1,2048)[c]));
        out[(size_t)item0*VDIM + c]     = cs0 * g0;
        out[(size_t)(item0+1)*VDIM + c] = cs1 * g1;
    }
    if (tid < ADIM){
        out[(size_t)BT*VDIM + (size_t)item0*ADIM + tid]     = FB(0,3328)[tid];
        out[(size_t)BT*VDIM + (size_t)(item0+1)*ADIM + tid] = FB(1,3328)[tid];
    }
#undef FB
}

extern "C" void kernel_launch(void* const* d_in, const int* in_sizes, int n_in,
                              void* d_out, int out_size)
{
    const float* video = (const float*)d_in[0];
    const float* audio = (const float*)d_in[1];
    const float* wq    = (const float*)d_in[2];  const float* bq    = (const float*)d_in[3];
    const float* wk    = (const float*)d_in[4];  const float* bk    = (const float*)d_in[5];
    const float* wv    = (const float*)d_in[6];  const float* bv    = (const float*)d_in[7];
    const float* ln_g  = (const float*)d_in[8];  const float* ln_b  = (const float*)d_in[9];
    const float* w_ave = (const float*)d_in[10]; const float* b_ave = (const float*)d_in[11];
    const float* w_v3  = (const float*)d_in[12]; const float* b_v3  = (const float*)d_in[13];
    const float* w_avt = (const float*)d_in[14]; const float* b_avt = (const float*)d_in[15];
    const float* w_a1  = (const float*)d_in[16]; const float* b_a1  = (const float*)d_in[17];
    const float* w_v1  = (const float*)d_in[18]; const float* b_v1  = (const float*)d_in[19];
    const float* w_bn  = (const float*)d_in[20]; const float* b_bn  = (const float*)d_in[21];
    const float* w_ca  = (const float*)d_in[22]; const float* b_ca  = (const float*)d_in[23];
    const float* w_v2  = (const float*)d_in[24]; const float* b_v2  = (const float*)d_in[25];
    const float* w_a2  = (const float*)d_in[26]; const float* b_a2  = (const float*)d_in[27];
    const float* w_sa  = (const float*)d_in[28]; const float* b_sa  = (const float*)d_in[29];
    float* out = (float*)d_out;

    repack_all<<<5504, 256>>>(wq, wk, wv, w_v3, w_v1, w_v2,
                              w_a1, w_a2, w_ave, w_bn, w_ca);

    cudaFuncSetAttribute(fused, cudaFuncAttributeMaxDynamicSharedMemorySize, SMEM_TOTAL);
    fused<<<BT/2, 512, SMEM_TOTAL>>>(video, audio, bq, bk, bv, ln_g, ln_b,
                                     b_ave, b_v3, w_avt, b_avt, b_a1, b_v1,
                                     b_bn, b_ca, b_v2, b_a2, w_sa, b_sa, out);
}

// round 17
// speedup vs baseline: 1.3134x; 1.0690x over previous
#include <cuda_runtime.h>
#include <cuda_fp16.h>
#include <math.h>

#define NB 256
#define NT 10
#define BT 2560
#define NP 49
#define VDIM 512
#define HDIM 256
#define ADIM 128
#define LDAH 520
#define LDAHB 1040
#define LDQK2 264
#define LDATT 72
#define LDATTB 144

static __device__ __half g_wph[1409024];

#define OFF_QK   0
#define OFF_WV   131072
#define OFF_V31  393216
#define OFF_V2   786432
#define OFF_GA1  917504
#define OFF_GA2  983040
#define OFF_GAVE 1015808
#define OFF_GBN  1146880
#define OFF_GCA  1277952

// smem: sA [0,133120) | R1 [133120,200704): qk(67584)|sZp(65536)|fbf(28672)
//       R2 [200704,219136): C/attn 2 x 64 x LDATT halves
#define SM_R1 133120
#define SM_R2 200704
#define SMEM_TOTAL 219136

__device__ __forceinline__ unsigned smem_u32(const void* p){
    unsigned a;
    asm("{ .reg .u64 t; cvta.to.shared.u64 t, %1; cvt.u32.u64 %0, t; }" : "=r"(a) : "l"(p));
    return a;
}
__device__ __forceinline__ float wsum(float v){
#pragma unroll
    for (int s = 16; s > 0; s >>= 1) v += __shfl_xor_sync(0xffffffffu, v, s);
    return v;
}
__device__ __forceinline__ float wmax(float v){
#pragma unroll
    for (int s = 16; s > 0; s >>= 1) v = fmaxf(v, __shfl_xor_sync(0xffffffffu, v, s));
    return v;
}
__device__ __forceinline__ void mma16(float (&d)[4], unsigned a0, unsigned a1,
                                      unsigned a2, unsigned a3, unsigned b0, unsigned b1){
    asm volatile("mma.sync.aligned.m16n8k16.row.col.f32.f16.f16.f32 "
        "{%0,%1,%2,%3},{%4,%5,%6,%7},{%8,%9},{%0,%1,%2,%3};"
        : "+f"(d[0]), "+f"(d[1]), "+f"(d[2]), "+f"(d[3])
        : "r"(a0), "r"(a1), "r"(a2), "r"(a3), "r"(b0), "r"(b1));
}
__device__ __forceinline__ void ldsm4(unsigned (&r)[4], unsigned a){
    asm volatile("ldmatrix.sync.aligned.m8n8.x4.shared.b16 {%0,%1,%2,%3}, [%4];"
        : "=r"(r[0]), "=r"(r[1]), "=r"(r[2]), "=r"(r[3]) : "r"(a));
}

// Quad-rowblock GEMM, ldmatrix A, register double-buffered B prefetch.
template<int KH, class E>
__device__ __forceinline__ void gemm_quad(unsigned ab0, unsigned ab1,
                                          unsigned ab2, unsigned ab3,
                                          const __half* __restrict__ B, int ntb, E epi)
{
    const int lane = threadIdx.x & 31;
    constexpr int nk32 = KH >> 5;
    float acc[4][4][4];
#pragma unroll
    for (int bl = 0; bl < 4; bl++)
#pragma unroll
    for (int nt = 0; nt < 4; nt++)
#pragma unroll
    for (int i = 0; i < 4; i++) acc[bl][nt][i] = 0.f;

    const unsigned ab[4] = {ab0, ab1, ab2, ab3};
    const __half* Bp = B + (size_t)ntb * nk32 * 256 + lane * 8;
    uint4 bv[4];
#pragma unroll
    for (int nt = 0; nt < 4; nt++)
        bv[nt] = *(const uint4*)(Bp + (size_t)nt * nk32 * 256);
#pragma unroll
    for (int k32 = 0; k32 < nk32; k32++){
        uint4 bn[4];
        if (k32 + 1 < nk32){
#pragma unroll
            for (int nt = 0; nt < 4; nt++)
                bn[nt] = *(const uint4*)(Bp + ((size_t)nt * nk32 + k32 + 1) * 256);
        }
#pragma unroll
        for (int s = 0; s < 2; s++){
            const unsigned ko = (unsigned)(k32*64 + s*32);
            unsigned R[4][4];
#pragma unroll
            for (int bl = 0; bl < 4; bl++) ldsm4(R[bl], ab[bl] + ko);
#pragma unroll
            for (int nt = 0; nt < 4; nt++){
                unsigned b0 = s ? bv[nt].z : bv[nt].x;
                unsigned b1 = s ? bv[nt].w : bv[nt].y;
#pragma unroll
                for (int bl = 0; bl < 4; bl++)
                    mma16(acc[bl][nt], R[bl][0], R[bl][1], R[bl][2], R[bl][3], b0, b1);
            }
        }
#pragma unroll
        for (int nt = 0; nt < 4; nt++) bv[nt] = bn[nt];
    }
    epi(acc);
}

// 16-warp 2-item GEMV, fp16 weights; x vectors held in registers.
template<int K, class F>
__device__ __forceinline__ void gemv16h(const __half* __restrict__ W,
                                        const float* __restrict__ x0,
                                        const float* __restrict__ x1, int N, F f){
    const int lane = threadIdx.x & 31, warp = threadIdx.x >> 5;
    float4 xr0[K/128], xr1[K/128];
#pragma unroll
    for (int c = 0; c < K/128; c++){
        xr0[c] = ((const float4*)x0)[lane + 32*c];
        xr1[c] = ((const float4*)x1)[lane + 32*c];
    }
    for (int j = warp; j < N; j += 16){
        const __half* wr = W + (size_t)j * K;
        float s0 = 0.f, s1 = 0.f;
#pragma unroll
        for (int c = 0; c < K/128; c++){
            uint2 w = *(const uint2*)(wr + (lane + 32*c)*4);
            float2 a01 = __half22float2(*(__half2*)&w.x);
            float2 a23 = __half22float2(*(__half2*)&w.y);
            s0 = fmaf(a01.x,xr0[c].x, fmaf(a01.y,xr0[c].y, fmaf(a23.x,xr0[c].z, fmaf(a23.y,xr0[c].w, s0))));
            s1 = fmaf(a01.x,xr1[c].x, fmaf(a01.y,xr1[c].y, fmaf(a23.x,xr1[c].z, fmaf(a23.y,xr1[c].w, s1))));
        }
        s0 = wsum(s0); s1 = wsum(s1);
        if (lane == 0) f(j, s0, s1);
    }
}

__global__ void repack_all(const float* __restrict__ wq, const float* __restrict__ wk,
                           const float* __restrict__ wv, const float* __restrict__ w_v3,
                           const float* __restrict__ w_v1, const float* __restrict__ w_v2,
                           const float* __restrict__ w_a1, const float* __restrict__ w_a2,
                           const float* __restrict__ w_ave, const float* __restrict__ w_bn,
                           const float* __restrict__ w_ca)
{
    int i = blockIdx.x*blockDim.x + threadIdx.x;
    if (i >= 1409024) return;
    if (i >= 917504){
        const float* src; int base;
        if      (i < 983040)  { src = w_a1;  base = OFF_GA1; }
        else if (i < 1015808) { src = w_a2;  base = OFF_GA2; }
        else if (i < 1146880) { src = w_ave; base = OFF_GAVE; }
        else if (i < 1277952) { src = w_bn;  base = OFF_GBN; }
        else                  { src = w_ca;  base = OFF_GCA; }
        g_wph[i] = __float2half(src[i - base]);
        return;
    }
    const float* src; int base;
    if      (i < 65536)  { src = wq;   base = 0; }
    else if (i < 131072) { src = wk;   base = 65536; }
    else if (i < 393216) { src = wv;   base = 131072; }
    else if (i < 524288) { src = w_v3; base = 393216; }
    else if (i < 786432) { src = w_v1; base = 524288; }
    else                 { src = w_v2; base = 786432; }
    int li = i - base;
    int h = li & 7, r = li >> 3;
    int lane = r & 31; r >>= 5;
    int k32 = r & 15;  int nt = r >> 4;
    int g = lane >> 2, t = lane & 3;
    int s = h >> 2, hi = (h >> 1) & 1, lo = h & 1;
    g_wph[i] = __float2half(src[(size_t)(nt*8 + g)*512 + k32*32 + 16*s + 8*hi + 2*t + lo]);
}

__global__ void __launch_bounds__(512, 1)
fused(const float* __restrict__ video, const float* __restrict__ audio,
      const float* __restrict__ bq, const float* __restrict__ bk,
      const float* __restrict__ bvb,
      const float* __restrict__ ln_g, const float* __restrict__ ln_b,
      const float* __restrict__ b_ave, const float* __restrict__ b_v3,
      const float* __restrict__ w_avatt, const float* __restrict__ b_avatt,
      const float* __restrict__ b_a1, const float* __restrict__ b_v1,
      const float* __restrict__ b_bn, const float* __restrict__ b_ca,
      const float* __restrict__ b_v2, const float* __restrict__ b_a2,
      const float* __restrict__ w_sa, const float* __restrict__ b_sa,
      float* __restrict__ out)
{
    extern __shared__ __align__(16) unsigned char smraw[];
    __half* sA   = (__half*)smraw;
    __half* sQKb = (__half*)(smraw + SM_R1);
    __half* sZp  = (__half*)(smraw + SM_R1);
    float*  fbf  = (float*)(smraw + SM_R1);
    __half* sAtb = (__half*)(smraw + SM_R2);
#define FB(it, off) (fbf + (it)*3584 + (off))

    const int tid = threadIdx.x, lane = tid & 31, warp = tid >> 5;
    const int g = lane >> 2, t = lane & 3;
    const int item0 = blockIdx.x * 2;
    const float* vf0 = video + (size_t)item0 * NP * VDIM;
    const float* vf1 = vf0 + NP * VDIM;
    const unsigned smb = smem_u32(smraw);
    const unsigned laneOff  = (unsigned)((lane & 15) * LDAHB  + ((lane >> 4) << 4));
    const unsigned laneOffA = (unsigned)((lane & 15) * LDATTB + ((lane >> 4) << 4));
    const int mt2 = warp & 1, ng8 = warp >> 1;

#pragma unroll
    for (int it = 0; it < 2; it++){
        __half* sAi = sA + it*64*LDAH;
        const float* vf = it ? vf1 : vf0;
        for (int i = tid; i < NP*VDIM/4; i += 512){
            int row = i >> 7, c4 = (i & 127) << 2;
            float4 v = ((const float4*)vf)[i];
            __half2 h01 = __floats2half2_rn(v.x, v.y);
            __half2 h23 = __floats2half2_rn(v.z, v.w);
            *(uint2*)(sAi + row*LDAH + c4) = make_uint2(*(unsigned*)&h01, *(unsigned*)&h23);
        }
        for (int i = tid; i < 15*LDAH; i += 512) sAi[49*LDAH + i] = __float2half(0.f);
    }
    __syncthreads();

    // ---- q|k GEMM ----
    {
        const int col0 = ng8*32;
        unsigned a0 = smb + (unsigned)(mt2*32)*LDAHB + laneOff;
        unsigned a1 = a0 + 16*LDAHB;
        unsigned a2 = a0 + 64*LDAHB;
        unsigned a3 = a2 + 16*LDAHB;
        gemm_quad<512>(a0, a1, a2, a3, g_wph + OFF_QK, col0 >> 3,
            [&](float (&a)[4][4][4]){
#pragma unroll
                for (int bl = 0; bl < 4; bl++){
                    int it = bl >> 1;
                    __half* dstb = sQKb + it*64*LDQK2;
                    int rb = mt2*32 + (bl & 1)*16;
#pragma unroll
                    for (int h2 = 0; h2 < 2; h2++){
                        int r = rb + h2*8 + g;
#pragma unroll
                        for (int nt = 0; nt < 4; nt++){
                            int c = col0 + nt*8 + 2*t;
                            float bb0 = (c < 128) ? bq[c] : bk[c-128];
                            float bb1 = (c < 128) ? bq[c+1] : bk[c-127];
                            *(__half2*)(dstb + r*LDQK2 + c) =
                                __floats2half2_rn(a[bl][nt][h2*2] + bb0,
                                                  a[bl][nt][h2*2+1] + bb1);
                        }
                    }
                }
            });
    }
    __syncthreads();

    // ---- logits C = q k^T via mma -> fp16 into sAtb ----
    {
        const int itq = warp >> 3, mtq = (warp >> 1) & 3, ngq = warp & 1;
        unsigned qb = smb + SM_R1 + (unsigned)itq*33792;
        unsigned arow = qb + (unsigned)((mtq*16 + (lane & 15))*528 + ((lane >> 4) << 4));
        unsigned brow0 = qb + 256 + (unsigned)((ngq*32 +      (lane & 15))*528 + ((lane >> 4) << 4));
        unsigned brow1 = brow0 + 16*528;
        float acc[4][4];
#pragma unroll
        for (int nt = 0; nt < 4; nt++)
#pragma unroll
        for (int i = 0; i < 4; i++) acc[nt][i] = 0.f;
#pragma unroll
        for (int st = 0; st < 8; st++){
            unsigned A[4], B0[4], B1[4];
            ldsm4(A,  arow  + st*32);
            ldsm4(B0, brow0 + st*32);
            ldsm4(B1, brow1 + st*32);
            mma16(acc[0], A[0],A[1],A[2],A[3], B0[0], B0[2]);
            mma16(acc[1], A[0],A[1],A[2],A[3], B0[1], B0[3]);
            mma16(acc[2], A[0],A[1],A[2],A[3], B1[0], B1[2]);
            mma16(acc[3], A[0],A[1],A[2],A[3], B1[1], B1[3]);
        }
        __half* Cb = sAtb + itq*64*LDATT;
#pragma unroll
        for (int nt = 0; nt < 4; nt++)
#pragma unroll
        for (int h2 = 0; h2 < 2; h2++){
            int r = mtq*16 + h2*8 + g;
            int c = ngq*32 + nt*8 + 2*t;
            *(__half2*)(Cb + r*LDATT + c) =
                __floats2half2_rn(acc[nt][h2*2], acc[nt][h2*2+1]);
        }
    }
    __syncthreads();

    // ---- softmax rows in place; zero pad rows/keys ----
    for (int R = warp; R < 128; R += 16){
        int it = R >> 6, n = R & 63;
        __half* att = sAtb + it*64*LDATT + n*LDATT;
        int m1 = lane + 32;
        if (n < NP){
            float l0 = __half2float(att[lane]);
            bool v = m1 < NP;
            float l1 = v ? __half2float(att[m1]) : -1e30f;
            float mx = wmax(fmaxf(l0, l1));
            float e0 = expf(l0 - mx);
            float e1 = v ? expf(l1 - mx) : 0.f;
            float s = wsum(e0 + e1);
            float inv = 1.f / s;
            att[lane] = __float2half(e0 * inv);
            att[m1] = __float2half(v ? e1 * inv : 0.f);
        } else {
            att[lane] = __float2half(0.f);
            att[m1]   = __float2half(0.f);
        }
    }
    __syncthreads();

    // ---- per item: Z -> sZp; attn@Z -> sA (pre-LN) ----
    for (int it = 0; it < 2; it++){
        const float* vf = it ? vf1 : vf0;
        __half* sAw = sA + (size_t)it*64*LDAH;
        {
            const int col0 = warp*32;
            unsigned a0 = smb + (unsigned)(it*64)*LDAHB + laneOff;
            gemm_quad<512>(a0, a0+16*LDAHB, a0+32*LDAHB, a0+48*LDAHB,
                           g_wph + OFF_WV, col0 >> 3,
                [&](float (&a)[4][4][4]){
#pragma unroll
                    for (int bl = 0; bl < 4; bl++)
#pragma unroll
                    for (int h2 = 0; h2 < 2; h2++){
                        int m = bl*16 + h2*8 + g;
                        int k32 = m >> 5, b = m & 31;
                        int sb = b >> 4, rem = b & 15;
                        int hb = rem >> 3, tp = (rem >> 1) & 3, lo2 = rem & 1;
#pragma unroll
                        for (int nt = 0; nt < 4; nt++)
#pragma unroll
                        for (int i = 0; i < 2; i++){
                            int lc = col0 + nt*8 + 2*t + i;
                            int off = (((lc >> 3)*2 + k32)*32 + ((lc & 7)*4 + tp))*8
                                      + sb*4 + hb*2 + lo2;
                            sZp[off] = __float2half(a[bl][nt][h2*2+i]);
                        }
                    }
                });
        }
        __syncthreads();
        {
            const int col0 = warp*32;
            unsigned a0 = smb + SM_R2 + (unsigned)(it*64)*LDATTB + laneOffA;
            gemm_quad<64>(a0, a0+16*LDATTB, a0+32*LDATTB, a0+48*LDATTB,
                          sZp, col0 >> 3,
                [&](float (&a)[4][4][4]){
#pragma unroll
                    for (int bl = 0; bl < 4; bl++)
#pragma unroll
                    for (int h2 = 0; h2 < 2; h2++){
                        int n = bl*16 + h2*8 + g;
                        if (n < NP){
#pragma unroll
                            for (int nt = 0; nt < 4; nt++){
                                int c = col0 + nt*8 + 2*t;
                                float v0 = a[bl][nt][h2*2]   + bvb[c]   + vf[n*VDIM + c];
                                float v1 = a[bl][nt][h2*2+1] + bvb[c+1] + vf[n*VDIM + c+1];
                                *(__half2*)(sAw + n*LDAH + c) = __floats2half2_rn(v0, v1);
                            }
                        }
                    }
                });
        }
        __syncthreads();
    }

    // ---- LayerNorm in place ----
    for (int R = warp; R < 2*NP; R += 16){
        int it = (R >= NP) ? 1 : 0;
        int n = R - it*NP;
        __half* row = sA + (size_t)it*64*LDAH + n*LDAH;
        float s = 0.f, s2 = 0.f;
        for (int j = lane; j < VDIM; j += 32){
            float v = __half2float(row[j]);
            s += v; s2 = fmaf(v, v, s2);
        }
        s = wsum(s); s2 = wsum(s2);
        float mu = s * (1.f/VDIM);
        float var = s2 * (1.f/VDIM) - mu*mu;
        float rs = rsqrtf(var + 1e-5f);
        for (int j = lane; j < VDIM; j += 32){
            float v = __half2float(row[j]);
            row[j] = __float2half((v - mu) * rs * ln_g[j] + ln_b[j]);
        }
    }
    __syncthreads();
    {
        int b0 = item0 / NT, t0 = item0 % NT;
        int b1 = (item0+1) / NT, t1 = (item0+1) % NT;
        const float* ap0 = audio + ((size_t)t0 * NB + b0) * ADIM;
        const float* ap1 = audio + ((size_t)t1 * NB + b1) * ADIM;
        if (tid < ADIM){ FB(0,3328)[tid] = ap0[tid]; FB(1,3328)[tid] = ap1[tid]; }
        FB(0,1536)[tid] = 0.f;
        FB(1,1536)[tid] = 0.f;
        if (tid < 64){
#pragma unroll
            for (int it = 0; it < 2; it++){
                FB(it,3456)[tid] = (tid < NP) ? b_avatt[0] : 0.f;
                FB(it,3520)[tid] = (tid < NP) ? b_sa[0]   : 0.f;
            }
        }
    }
    __syncthreads();

    // ---- P1: colm, aq1, aq2 ----
    {
        int c = tid;
        float s0 = 0.f, s1 = 0.f;
        for (int n = 0; n < NP; n++){
            s0 += __half2float(sA[n*LDAH + c]);
            s1 += __half2float(sA[(64+n)*LDAH + c]);
        }
        FB(0,0)[c] = s0 * (1.f/NP);
        FB(1,0)[c] = s1 * (1.f/NP);
    }
    gemv16h<ADIM>(g_wph + OFF_GA1, FB(0,3328), FB(1,3328), 512,
        [&](int j, float s0, float s1){
            FB(0,512)[j] = fmaxf(s0 + b_a1[j], 0.f);
            FB(1,512)[j] = fmaxf(s1 + b_a1[j], 0.f);
        });
    gemv16h<ADIM>(g_wph + OFF_GA2, FB(0,3328), FB(1,3328), 256,
        [&](int j, float s0, float s1){
            FB(0,2816)[j] = fmaxf(s0 + b_a2[j], 0.f);
            FB(1,2816)[j] = fmaxf(s1 + b_a2[j], 0.f);
        });
    __syncthreads();
    gemv16h<VDIM>(g_wph + OFF_GAVE, FB(0,0), FB(1,0), 256,
        [&](int j, float s0, float s1){
            FB(0,2560)[j] = fmaxf(s0 + b_ave[j], 0.f);
            FB(1,2560)[j] = fmaxf(s1 + b_ave[j], 0.f);
        });
    __syncthreads();

    // ---- P3: [w_v3 | w_v1] GEMM, 3 passes of 256 ----
    {
        unsigned a0 = smb + (unsigned)(mt2*32)*LDAHB + laneOff;
        unsigned a1 = a0 + 16*LDAHB;
        unsigned a2 = a0 + 64*LDAHB;
        unsigned a3 = a2 + 16*LDAHB;
        for (int p = 0; p < 3; p++){
            const int col0 = p*256 + ng8*32;
            gemm_quad<512>(a0, a1, a2, a3, g_wph + OFF_V31, col0 >> 3,
                [&](float (&a)[4][4][4]){
                    if (col0 < 256){
#pragma unroll
                        for (int bl = 0; bl < 4; bl++){
                            int it = bl >> 1;
                            int rb = mt2*32 + (bl & 1)*16;
#pragma unroll
                            for (int h2 = 0; h2 < 2; h2++){
                                int r = rb + h2*8 + g;
                                float v = 0.f;
#pragma unroll
                                for (int nt = 0; nt < 4; nt++)
#pragma unroll
                                for (int i = 0; i < 2; i++){
                                    int c = col0 + nt*8 + 2*t + i;
                                    v += fmaxf(a[bl][nt][h2*2+i] + b_v3[c], 0.f)
                                         * FB(it,2560)[c] * w_avatt[c];
                                }
                                v += __shfl_xor_sync(0xffffffffu, v, 1);
                                v += __shfl_xor_sync(0xffffffffu, v, 2);
                                if (t == 0 && r < NP) atomicAdd(&FB(it,3456)[r], v);
                            }
                        }
                    } else {
#pragma unroll
                        for (int it = 0; it < 2; it++){
                            int rb0 = mt2*32, rb1 = mt2*32 + 16;
#pragma unroll
                            for (int nt = 0; nt < 4; nt++)
#pragma unroll
                            for (int i = 0; i < 2; i++){
                                int c = col0 - 256 + nt*8 + 2*t + i;
                                float bb = b_v1[c];
                                float pv = 0.f;
#pragma unroll
                                for (int h2 = 0; h2 < 2; h2++){
                                    float m0 = (rb0 + h2*8 + g < NP) ? 1.f : 0.f;
                                    float m1 = (rb1 + h2*8 + g < NP) ? 1.f : 0.f;
                                    pv += m0*fmaxf(a[it*2][nt][h2*2+i]   + bb, 0.f)
                                        + m1*fmaxf(a[it*2+1][nt][h2*2+i] + bb, 0.f);
                                }
                                pv += __shfl_xor_sync(0xffffffffu, pv, 4);
                                pv += __shfl_xor_sync(0xffffffffu, pv, 8);
                                pv += __shfl_xor_sync(0xffffffffu, pv, 16);
                                if (g == 0) atomicAdd(&FB(it,1536)[c], pv);
                            }
                        }
                    }
                });
        }
    }
    __syncthreads();

    // ---- finalize colv; self softmax ----
    {
        int it = tid >> 8, c2 = (tid & 255)*2;
#pragma unroll
        for (int d = 0; d < 2; d++){
            int c = c2 + d;
            FB(it,1536)[c] = FB(it,1536)[c] * (1.f/NP) * FB(it,512)[c];
        }
    }
    if (warp < 2){
        float* sl = FB(warp,3456);
        float v0 = tanhf(sl[lane]);
        float v1 = (lane + 32 < NP) ? tanhf(sl[lane+32]) : -1e30f;
        float mx = wmax(fmaxf(v0, v1));
        float e0 = expf(v0 - mx);
        float e1 = (lane + 32 < NP) ? expf(v1 - mx) : 0.f;
        float s = wsum(e0 + e1);
        sl[lane] = e0 / s;
        if (lane + 32 < NP) sl[lane+32] = e1 / s;
    }
    __syncthreads();
    gemv16h<VDIM>(g_wph + OFF_GBN, FB(0,1536), FB(1,1536), 256,
        [&](int j, float s0, float s1){
            FB(0,3072)[j] = fmaxf(s0 + b_bn[j], 0.f);
            FB(1,3072)[j] = fmaxf(s1 + b_bn[j], 0.f);
        });
    __syncthreads();

    // ---- P5: sav ; ch ----
    {
        int c = tid;
        float s0 = 0.f, s1 = 0.f;
        for (int n = 0; n < NP; n++){
            s0 = fmaf(FB(0,3456)[n], __half2float(sA[n*LDAH + c]), s0);
            s1 = fmaf(FB(1,3456)[n], __half2float(sA[(64+n)*LDAH + c]), s1);
        }
        FB(0,2048)[c] = s0; FB(1,2048)[c] = s1;
    }
    gemv16h<HDIM>(g_wph + OFF_GCA, FB(0,3072), FB(1,3072), 512,
        [&](int j, float s0, float s1){
            FB(0,1024)[j] = 1.f + 1.f/(1.f + expf(-(s0 + b_ca[j])));
            FB(1,1024)[j] = 1.f + 1.f/(1.f + expf(-(s1 + b_ca[j])));
        });
    __syncthreads();

    // ---- P6: c_att -> sA ----
#pragma unroll
    for (int it = 0; it < 2; it++){
        __half* sAi = sA + (size_t)it*64*LDAH;
        const float* vf = it ? vf1 : vf0;
        const float* ch = FB(it,1024);
        for (int i = tid; i < NP*VDIM/4; i += 512){
            int row = i >> 7, c4 = (i & 127) << 2;
            float4 v = ((const float4*)vf)[i];
            __half2 h01 = __floats2half2_rn(v.x*ch[c4],   v.y*ch[c4+1]);
            __half2 h23 = __floats2half2_rn(v.z*ch[c4+2], v.w*ch[c4+3]);
            *(uint2*)(sAi + row*LDAH + c4) = make_uint2(*(unsigned*)&h01, *(unsigned*)&h23);
        }
    }
    __syncthreads();

    // ---- P7: w_v2 GEMM -> spatial logits ----
    {
        const int col0 = ng8*32;
        unsigned a0 = smb + (unsigned)(mt2*32)*LDAHB + laneOff;
        unsigned a1 = a0 + 16*LDAHB;
        unsigned a2 = a0 + 64*LDAHB;
        unsigned a3 = a2 + 16*LDAHB;
        gemm_quad<512>(a0, a1, a2, a3, g_wph + OFF_V2, col0 >> 3,
            [&](float (&a)[4][4][4]){
#pragma unroll
                for (int bl = 0; bl < 4; bl++){
                    int it = bl >> 1;
                    int rb = mt2*32 + (bl & 1)*16;
#pragma unroll
                    for (int h2 = 0; h2 < 2; h2++){
                        int r = rb + h2*8 + g;
                        float v = 0.f;
#pragma unroll
                        for (int nt = 0; nt < 4; nt++)
#pragma unroll
                        for (int i = 0; i < 2; i++){
                            int c = col0 + nt*8 + 2*t + i;
                            v += fmaxf(a[bl][nt][h2*2+i] + b_v2[c], 0.f)
                                 * FB(it,2816)[c] * w_sa[c];
                        }
                        v += __shfl_xor_sync(0xffffffffu, v, 1);
                        v += __shfl_xor_sync(0xffffffffu, v, 2);
                        if (t == 0 && r < NP) atomicAdd(&FB(it,3520)[r], v);
                    }
                }
            });
    }
    __syncthreads();

    // ---- spatial softmax ----
    if (warp < 2){
        float* sp = FB(warp,3520);
        float v0 = tanhf(sp[lane]);
        float v1 = (lane + 32 < NP) ? tanhf(sp[lane+32]) : -1e30f;
        float mx = wmax(fmaxf(v0, v1));
        float e0 = expf(v0 - mx);
        float e1 = (lane + 32 < NP) ? expf(v1 - mx) : 0.f;
        float s = wsum(e0 + e1);
        sp[lane] = e0 / s;
        if (lane + 32 < NP) sp[lane+32] = e1 / s;
    }
    __syncthreads();

    // ---- outputs ----
    {
        int c = tid;
        float cs0 = 0.f, cs1 = 0.f;
        for (int n = 0; n < NP; n++){
            cs0 = fmaf(FB(0,3520)[n], __half2float(sA[n*LDAH + c]), cs0);
            cs1 = fmaf(FB(1,3520)[n], __half2float(sA[(64+n)*LDAH + c]), cs1);
        }
        float g0 = 1.f + 0.5f/(1.f + expf(-FB(0,2048)[c]));
        float g1 = 1.f + 0.5f/(1.f + expf(-FB(1,2048)[c]));
        out[(size_t)item0*VDIM + c]     = cs0 * g0;
        out[(size_t)(item0+1)*VDIM + c] = cs1 * g1;
    }
    if (tid < ADIM){
        out[(size_t)BT*VDIM + (size_t)item0*ADIM + tid]     = FB(0,3328)[tid];
        out[(size_t)BT*VDIM + (size_t)(item0+1)*ADIM + tid] = FB(1,3328)[tid];
    }
#undef FB
}

extern "C" void kernel_launch(void* const* d_in, const int* in_sizes, int n_in,
                              void* d_out, int out_size)
{
    const float* video = (const float*)d_in[0];
    const float* audio = (const float*)d_in[1];
    const float* wq    = (const float*)d_in[2];  const float* bq    = (const float*)d_in[3];
    const float* wk    = (const float*)d_in[4];  const float* bk    = (const float*)d_in[5];
    const float* wv    = (const float*)d_in[6];  const float* bv    = (const float*)d_in[7];
    const float* ln_g  = (const float*)d_in[8];  const float* ln_b  = (const float*)d_in[9];
    const float* w_ave = (const float*)d_in[10]; const float* b_ave = (const float*)d_in[11];
    const float* w_v3  = (const float*)d_in[12]; const float* b_v3  = (const float*)d_in[13];
    const float* w_avt = (const float*)d_in[14]; const float* b_avt = (const float*)d_in[15];
    const float* w_a1  = (const float*)d_in[16]; const float* b_a1  = (const float*)d_in[17];
    const float* w_v1  = (const float*)d_in[18]; const float* b_v1  = (const float*)d_in[19];
    const float* w_bn  = (const float*)d_in[20]; const float* b_bn  = (const float*)d_in[21];
    const float* w_ca  = (const float*)d_in[22]; const float* b_ca  = (const float*)d_in[23];
    const float* w_v2  = (const float*)d_in[24]; const float* b_v2  = (const float*)d_in[25];
    const float* w_a2  = (const float*)d_in[26]; const float* b_a2  = (const float*)d_in[27];
    const float* w_sa  = (const float*)d_in[28]; const float* b_sa  = (const float*)d_in[29];
    float* out = (float*)d_out;

    repack_all<<<5504, 256>>>(wq, wk, wv, w_v3, w_v1, w_v2,
                              w_a1, w_a2, w_ave, w_bn, w_ca);

    cudaFuncSetAttribute(fused, cudaFuncAttributeMaxDynamicSharedMemorySize, SMEM_TOTAL);
    fused<<<BT/2, 512, SMEM_TOTAL>>>(video, audio, bq, bk, bv, ln_g, ln_b,
                                     b_ave, b_v3, w_avt, b_avt, b_a1, b_v1,
                                     b_bn, b_ca, b_v2, b_a2, w_sa, b_sa, out);
}